// round 11
// baseline (speedup 1.0000x reference)
#include <cuda_runtime.h>
#include <cuda_bf16.h>
#include <cstdint>
#include <math.h>

constexpr int cN = 4, cH = 128, cW = 256;
constexpr int CIN1 = 96,  COUT1 = 128;
constexpr int CIN2 = 128, COUT2 = 144;
constexpr int HW = cH * cW, Hp = cH + 2, Wp = cW + 2;
constexpr int NPX = cN * Hp * Wp;

// Static scratch (16B-aligned for cp.async / uint4)
__device__ __align__(256) __nv_bfloat16 g_A1h[(size_t)NPX * CIN1];
__device__ __align__(256) __nv_bfloat16 g_A1l[(size_t)NPX * CIN1];
__device__ __align__(256) __nv_bfloat16 g_A2h[(size_t)NPX * CIN2];
__device__ __align__(256) __nv_bfloat16 g_A2l[(size_t)NPX * CIN2];
__device__ __align__(256) __nv_bfloat16 g_W1[9 * 3 * 2 * COUT1 * 32];
__device__ __align__(256) __nv_bfloat16 g_W2[9 * 4 * 2 * COUT2 * 32];
__device__ __align__(256) float g_mask[(size_t)cN * COUT2 * HW];

// ---------------- helpers ----------------------------------------------------
__device__ __forceinline__ uint32_t smem_u32(const void* p) {
    uint32_t a;
    asm("{ .reg .u64 t; cvta.to.shared.u64 t, %1; cvt.u32.u64 %0, t; }" : "=r"(a) : "l"(p));
    return a;
}
__device__ __forceinline__ void cpa16(uint32_t s, const void* g) {
    asm volatile("cp.async.cg.shared.global [%0], [%1], 16;" :: "r"(s), "l"(g) : "memory");
}
__device__ __forceinline__ void ldsm_x4(uint32_t a, uint32_t* r) {
    asm volatile("ldmatrix.sync.aligned.m8n8.x4.shared.b16 {%0,%1,%2,%3}, [%4];"
                 : "=r"(r[0]), "=r"(r[1]), "=r"(r[2]), "=r"(r[3]) : "r"(a));
}
__device__ __forceinline__ void ldsm_x2(uint32_t a, uint32_t* r) {
    asm volatile("ldmatrix.sync.aligned.m8n8.x2.shared.b16 {%0,%1}, [%2];"
                 : "=r"(r[0]), "=r"(r[1]) : "r"(a));
}
__device__ __forceinline__ void mma_bf16(float* d, const uint32_t* a, uint32_t b0, uint32_t b1) {
    asm volatile("mma.sync.aligned.m16n8k16.row.col.f32.bf16.bf16.f32 "
        "{%0,%1,%2,%3}, {%4,%5,%6,%7}, {%8,%9}, {%0,%1,%2,%3};"
        : "+f"(d[0]), "+f"(d[1]), "+f"(d[2]), "+f"(d[3])
        : "r"(a[0]), "r"(a[1]), "r"(a[2]), "r"(a[3]), "r"(b0), "r"(b1));
}
__device__ __forceinline__ void split2(float a, float b, uint32_t& h, uint32_t& l) {
    __nv_bfloat162 hb = __floats2bfloat162_rn(a, b);
    __nv_bfloat162 lb = __floats2bfloat162_rn(a - __bfloat162float(hb.x),
                                              b - __bfloat162float(hb.y));
    h = *reinterpret_cast<uint32_t*>(&hb);
    l = *reinterpret_cast<uint32_t*>(&lb);
}

// ---------------- prep: feat -> padded hi/lo planes [flat][96] --------------
__global__ __launch_bounds__(128) void split_feat_kernel(const float* __restrict__ feat)
{
    int flat = blockIdx.x * 128 + threadIdx.x;
    if (flat >= NPX) return;
    int xp = flat % Wp, yp = (flat / Wp) % Hp, n = flat / (Hp * Wp);
    bool interior = (yp >= 1 && yp <= cH && xp >= 1 && xp <= cW);
    __nv_bfloat16* dh = g_A1h + (size_t)flat * CIN1;
    __nv_bfloat16* dl = g_A1l + (size_t)flat * CIN1;
    #pragma unroll
    for (int c = 0; c < 3; c++) {
        uint32_t hw[16], lw[16];
        if (interior) {
            const float* src = feat + ((size_t)(n * CIN1 + c * 32) * cH + (yp - 1)) * cW + (xp - 1);
            #pragma unroll
            for (int i = 0; i < 16; i++)
                split2(src[(size_t)(2 * i) * HW], src[(size_t)(2 * i + 1) * HW], hw[i], lw[i]);
        } else {
            #pragma unroll
            for (int i = 0; i < 16; i++) { hw[i] = 0; lw[i] = 0; }
        }
        #pragma unroll
        for (int j = 0; j < 4; j++) {
            *reinterpret_cast<uint4*>(dh + c * 32 + j * 8) = *reinterpret_cast<uint4*>(hw + j * 4);
            *reinterpret_cast<uint4*>(dl + c * 32 + j * 8) = *reinterpret_cast<uint4*>(lw + j * 4);
        }
    }
}

__global__ __launch_bounds__(128) void halo2_kernel()
{
    int flat = blockIdx.x * 128 + threadIdx.x;
    if (flat >= NPX) return;
    int xp = flat % Wp, yp = (flat / Wp) % Hp;
    if (yp >= 1 && yp <= cH && xp >= 1 && xp <= cW) return;
    uint4 z = {0, 0, 0, 0};
    uint4* dh = reinterpret_cast<uint4*>(g_A2h + (size_t)flat * CIN2);
    uint4* dl = reinterpret_cast<uint4*>(g_A2l + (size_t)flat * CIN2);
    #pragma unroll
    for (int j = 0; j < 16; j++) { dh[j] = z; dl[j] = z; }
}

// weights OIHW fp32 -> [pos][chunk][slab(h,l)][co][32] bf16
template<int CIN, int NCO>
__global__ __launch_bounds__(256) void split_w_kernel(const float* __restrict__ wt,
                                                      __nv_bfloat16* __restrict__ out)
{
    constexpr int NCH = CIN / 32;
    int idx = blockIdx.x * 256 + threadIdx.x;
    if (idx >= 9 * NCH * 2 * NCO * 32) return;
    int k = idx & 31; int t = idx >> 5;
    int co = t % NCO; t /= NCO;
    int slab = t % 2;  t /= 2;
    int chunk = t % NCH;
    int pos = t / NCH;
    float w = wt[((size_t)co * CIN + chunk * 32 + k) * 9 + pos];
    __nv_bfloat16 h = __float2bfloat16(w);
    out[idx] = (slab == 0) ? h : __float2bfloat16(w - __bfloat162float(h));
}

// ---------------- HMMA conv: CTA = full 256-px row x NCO, 16 warps (8M x 2N) --
// Per 32-ci chunk: A (3 ky-rows x 258 px, hi+lo) staged ONCE; all 9 positions
// computed via row-shifted ldmatrix. Weights double-buffered per position.
template<int CIN, int NCO, bool EPI1>
__global__ __launch_bounds__(512, 1) void conv_mma_kernel(
    const __nv_bfloat16* __restrict__ Ah, const __nv_bfloat16* __restrict__ Al,
    const __nv_bfloat16* __restrict__ Wv, const float* __restrict__ bias,
    float* __restrict__ maskOut)
{
    constexpr int NCH = CIN / 32;
    constexpr int WN  = NCO / 2;                // co per warp-N group
    constexpr int NT  = NCO / 16;               // n-tiles per warp (8 / 9)
    constexpr int NPAIR = NT / 2;
    constexpr int APL = 3 * 260 * 80;           // one A plane (3 ky x 260 rows)
    constexpr int WBUF = 2 * NCO * 80;          // one W buffer (hi+lo slabs)
    constexpr int ACP = 2 * 3 * 258 * 4;        // cp.async count for A

    extern __shared__ __align__(16) char smem[];
    const uint32_t s0 = smem_u32(smem);
    const uint32_t sW = s0 + 2 * APL;

    const int tid = threadIdx.x, lane = tid & 31, wid = tid >> 5;
    const int warpM = wid & 7, warpN = wid >> 3;
    const int g = lane >> 4 ? 0 : 0;  (void)g;
    const int gr = lane >> 2;

    const uint32_t aoff = (uint32_t)((lane & 15) * 80 + (lane >> 4) * 16);
    const uint32_t boff = (uint32_t)((((lane >> 4) << 3) + (lane & 7)) * 80 + ((lane >> 3) & 1) * 16);
    const uint32_t boff2 = (uint32_t)((lane & 7) * 80 + ((lane >> 3) & 1) * 16);

    const int y = blockIdx.x, n = blockIdx.y;

    float acc[2][NT][4];
    #pragma unroll
    for (int mi = 0; mi < 2; mi++)
        #pragma unroll
        for (int ni = 0; ni < NT; ni++)
            #pragma unroll
            for (int j = 0; j < 4; j++) acc[mi][ni][j] = 0.0f;

    auto stageA = [&](int chunk) {
        const size_t rowb = (size_t)(n * Hp + y) * Wp;
        for (int idx = tid; idx < ACP; idx += 512) {
            int j = idx & 3, r = idx >> 2;          // r in [0, 1548)
            int px = r % 258, t = r / 258;           // t in [0, 6)
            int ky = t % 3, pl = t / 3;
            const __nv_bfloat16* src = (pl ? Al : Ah) +
                (rowb + (size_t)ky * Wp + px) * CIN + chunk * 32 + j * 8;
            cpa16(s0 + pl * APL + (ky * 260 + px) * 80 + j * 16, src);
        }
    };
    auto stageW = [&](int pos, int chunk, int buf) {
        const __nv_bfloat16* ws = Wv + (size_t)(pos * NCH + chunk) * 2 * NCO * 32;
        for (int idx = tid; idx < 2 * NCO * 4; idx += 512) {
            int rr = idx >> 2, j = idx & 3;
            cpa16(sW + buf * WBUF + rr * 80 + j * 16, ws + rr * 32 + j * 8);
        }
    };
    auto compute = [&](int pos, int buf) {
        const int ky = pos / 3, kx = pos - ky * 3;
        const uint32_t Whb = sW + buf * WBUF;
        const uint32_t Wlb = Whb + NCO * 80;
        const uint32_t arow = (uint32_t)((ky * 260 + kx + warpM * 32) * 80);
        #pragma unroll
        for (int kh = 0; kh < 2; kh++) {
            const uint32_t ko = kh * 32;
            uint32_t ah[2][4], al[2][4];
            #pragma unroll
            for (int mi = 0; mi < 2; mi++) {
                const uint32_t ab = arow + (uint32_t)(mi * 16 * 80) + aoff + ko;
                ldsm_x4(s0 + ab, ah[mi]);
                ldsm_x4(s0 + APL + ab, al[mi]);
            }
            #pragma unroll
            for (int np = 0; np < NPAIR; np++) {
                const uint32_t nb = (uint32_t)((warpN * WN + np * 16) * 80) + boff + ko;
                uint32_t wh[4], wl[4];
                ldsm_x4(Whb + nb, wh);
                ldsm_x4(Wlb + nb, wl);
                #pragma unroll
                for (int mi = 0; mi < 2; mi++) {
                    mma_bf16(acc[mi][2 * np],     ah[mi], wh[0], wh[1]);
                    mma_bf16(acc[mi][2 * np + 1], ah[mi], wh[2], wh[3]);
                    mma_bf16(acc[mi][2 * np],     al[mi], wh[0], wh[1]);
                    mma_bf16(acc[mi][2 * np + 1], al[mi], wh[2], wh[3]);
                    mma_bf16(acc[mi][2 * np],     ah[mi], wl[0], wl[1]);
                    mma_bf16(acc[mi][2 * np + 1], ah[mi], wl[2], wl[3]);
                }
            }
            if (NT & 1) {   // odd tail tile (conv2: NT=9)
                const uint32_t nb = (uint32_t)((warpN * WN + (NT - 1) * 8) * 80) + boff2 + ko;
                uint32_t wh[2], wl[2];
                ldsm_x2(Whb + nb, wh);
                ldsm_x2(Wlb + nb, wl);
                #pragma unroll
                for (int mi = 0; mi < 2; mi++) {
                    mma_bf16(acc[mi][NT - 1], ah[mi], wh[0], wh[1]);
                    mma_bf16(acc[mi][NT - 1], al[mi], wh[0], wh[1]);
                    mma_bf16(acc[mi][NT - 1], ah[mi], wl[0], wl[1]);
                }
            }
        }
    };

    for (int c = 0; c < NCH; c++) {
        __syncthreads();                       // A buffer safe to overwrite
        stageA(c);
        stageW(0, c, 0);
        asm volatile("cp.async.commit_group;" ::: "memory");
        asm volatile("cp.async.wait_group 0;" ::: "memory");
        __syncthreads();
        for (int pos = 0; pos < 9; pos++) {
            if (pos < 8) {
                stageW(pos + 1, c, (pos + 1) & 1);
                asm volatile("cp.async.commit_group;" ::: "memory");
            }
            compute(pos, pos & 1);
            if (pos < 8)
                asm volatile("cp.async.wait_group 0;" ::: "memory");
            __syncthreads();
        }
    }

    // ---------------- epilogue ----------------
    const int t2 = (lane & 3) * 2;
    #pragma unroll
    for (int mi = 0; mi < 2; mi++) {
        #pragma unroll
        for (int rr = 0; rr < 2; rr++) {
            const int px = warpM * 32 + mi * 16 + gr + rr * 8;   // global x (0..255)
            if (EPI1) {
                const size_t flat = ((size_t)(n * Hp) + y + 1) * Wp + px + 1;
                __nv_bfloat16* dh = g_A2h + flat * CIN2;
                __nv_bfloat16* dl = g_A2l + flat * CIN2;
                #pragma unroll
                for (int ni = 0; ni < NT; ni++) {
                    const int co = warpN * WN + ni * 8 + t2;
                    float v0 = acc[mi][ni][rr * 2 + 0] + __ldg(bias + co);
                    float v1 = acc[mi][ni][rr * 2 + 1] + __ldg(bias + co + 1);
                    v0 = v0 > 0.f ? v0 : 0.1f * v0;
                    v1 = v1 > 0.f ? v1 : 0.1f * v1;
                    uint32_t h, l;
                    split2(v0, v1, h, l);
                    *reinterpret_cast<uint32_t*>(dh + co) = h;
                    *reinterpret_cast<uint32_t*>(dl + co) = l;
                }
            } else {
                #pragma unroll
                for (int ni = 0; ni < NT; ni++) {
                    const int co = warpN * WN + ni * 8 + t2;
                    float v0 = acc[mi][ni][rr * 2 + 0] + __ldg(bias + co);
                    float v1 = acc[mi][ni][rr * 2 + 1] + __ldg(bias + co + 1);
                    size_t o = ((size_t)(n * COUT2 + co) * cH + y) * cW + px;
                    maskOut[o]      = v0;
                    maskOut[o + HW] = v1;
                }
            }
        }
    }
}

// ---------------- softmax + convex upsample + pixel shuffle -----------------
__global__ __launch_bounds__(256)
void upsample_kernel(const float* __restrict__ flow,
                     const float* __restrict__ mask, float* __restrict__ out)
{
    const int idx = blockIdx.x * blockDim.x + threadIdx.x;
    if (idx >= cN * HW) return;
    const int x = idx % cW, y = (idx / cW) % cH, n = idx / HW;

    float fpx[9], fpy[9];
    #pragma unroll
    for (int ki = 0; ki < 3; ki++)
        #pragma unroll
        for (int kj = 0; kj < 3; kj++) {
            const int k = ki * 3 + kj;
            const int yy = y + ki - 1, xx = x + kj - 1;
            const bool ok = (unsigned)yy < (unsigned)cH && (unsigned)xx < (unsigned)cW;
            fpx[k] = ok ? 4.0f * flow[(n * 2 + 0) * HW + yy * cW + xx] : 0.0f;
            fpy[k] = ok ? 4.0f * flow[(n * 2 + 1) * HW + yy * cW + xx] : 0.0f;
        }
    const size_t base = (size_t)n * COUT2 * HW + y * cW + x;
    const int OH = 4 * cH, OW = 4 * cW;
    #pragma unroll
    for (int a = 0; a < 4; a++)
        #pragma unroll
        for (int b = 0; b < 4; b++) {
            float m[9], mx = -1e30f;
            #pragma unroll
            for (int k = 0; k < 9; k++) {
                m[k] = 0.25f * mask[base + (size_t)(k * 16 + a * 4 + b) * HW];
                mx = fmaxf(mx, m[k]);
            }
            float s = 0.0f;
            #pragma unroll
            for (int k = 0; k < 9; k++) { m[k] = __expf(m[k] - mx); s += m[k]; }
            const float inv = 1.0f / s;
            float ox = 0.0f, oy = 0.0f;
            #pragma unroll
            for (int k = 0; k < 9; k++) { ox += m[k] * fpx[k]; oy += m[k] * fpy[k]; }
            const int oyi = y * 4 + a, oxi = x * 4 + b;
            out[((size_t)(n * 2 + 0) * OH + oyi) * OW + oxi] = ox * inv;
            out[((size_t)(n * 2 + 1) * OH + oyi) * OW + oxi] = oy * inv;
        }
}

// ---------------------------------------------------------------------------
extern "C" void kernel_launch(void* const* d_in, const int* in_sizes, int n_in,
                              void* d_out, int out_size)
{
    (void)in_sizes; (void)n_in; (void)out_size;
    const float* flow = (const float*)d_in[0];
    const float* feat = (const float*)d_in[1];
    const float* w1   = (const float*)d_in[2];
    const float* b1   = (const float*)d_in[3];
    const float* w2   = (const float*)d_in[4];
    const float* b2   = (const float*)d_in[5];
    float* out = (float*)d_out;

    __nv_bfloat16 *a1h, *a1l, *a2h, *a2l, *w1s, *w2s; float* msk;
    cudaGetSymbolAddress((void**)&a1h, g_A1h);
    cudaGetSymbolAddress((void**)&a1l, g_A1l);
    cudaGetSymbolAddress((void**)&a2h, g_A2h);
    cudaGetSymbolAddress((void**)&a2l, g_A2l);
    cudaGetSymbolAddress((void**)&w1s, g_W1);
    cudaGetSymbolAddress((void**)&w2s, g_W2);
    cudaGetSymbolAddress((void**)&msk, g_mask);

    constexpr int APL = 3 * 260 * 80;
    constexpr int SM1 = 2 * APL + 2 * (2 * COUT1 * 80);   // 165,760
    constexpr int SM2 = 2 * APL + 2 * (2 * COUT2 * 80);   // 170,880
    cudaFuncSetAttribute(conv_mma_kernel<CIN1, COUT1, true>,
                         cudaFuncAttributeMaxDynamicSharedMemorySize, SM1);
    cudaFuncSetAttribute(conv_mma_kernel<CIN2, COUT2, false>,
                         cudaFuncAttributeMaxDynamicSharedMemorySize, SM2);

    split_feat_kernel<<<(NPX + 127) / 128, 128>>>(feat);
    halo2_kernel<<<(NPX + 127) / 128, 128>>>();
    split_w_kernel<CIN1, COUT1><<<(9 * 3 * 2 * COUT1 * 32 + 255) / 256, 256>>>(w1, w1s);
    split_w_kernel<CIN2, COUT2><<<(9 * 4 * 2 * COUT2 * 32 + 255) / 256, 256>>>(w2, w2s);

    conv_mma_kernel<CIN1, COUT1, true ><<<dim3(cH, cN), 512, SM1>>>(a1h, a1l, w1s, b1, msk);
    conv_mma_kernel<CIN2, COUT2, false><<<dim3(cH, cN), 512, SM2>>>(a2h, a2l, w2s, b2, msk);

    upsample_kernel<<<(cN * HW + 255) / 256, 256>>>(flow, msk, out);
}

// round 12
// speedup vs baseline: 2.4200x; 2.4200x over previous
#include <cuda_runtime.h>
#include <cuda_fp16.h>
#include <cstdint>
#include <math.h>

constexpr int cN = 4, cH = 128, cW = 256;
constexpr int CIN1 = 96,  COUT1 = 128;
constexpr int CIN2 = 128, COUT2 = 144;
constexpr int HW = cH * cW, Hp = cH + 2, Wp = cW + 2;
constexpr int NPX = cN * Hp * Wp;

// Static scratch (16B-aligned for cp.async / uint4) — single fp16 planes
__device__ __align__(256) __half g_A1[(size_t)NPX * CIN1];
__device__ __align__(256) __half g_A2[(size_t)NPX * CIN2];
__device__ __align__(256) __half g_W1[9 * 3 * COUT1 * 32];
__device__ __align__(256) __half g_W2[9 * 4 * COUT2 * 32];
__device__ __align__(256) float g_mask[(size_t)cN * COUT2 * HW];

// ---------------- helpers ----------------------------------------------------
__device__ __forceinline__ uint32_t smem_u32(const void* p) {
    uint32_t a;
    asm("{ .reg .u64 t; cvta.to.shared.u64 t, %1; cvt.u32.u64 %0, t; }" : "=r"(a) : "l"(p));
    return a;
}
__device__ __forceinline__ void cpa16(uint32_t s, const void* g) {
    asm volatile("cp.async.cg.shared.global [%0], [%1], 16;" :: "r"(s), "l"(g) : "memory");
}
__device__ __forceinline__ void ldsm_x4(uint32_t a, uint32_t* r) {
    asm volatile("ldmatrix.sync.aligned.m8n8.x4.shared.b16 {%0,%1,%2,%3}, [%4];"
                 : "=r"(r[0]), "=r"(r[1]), "=r"(r[2]), "=r"(r[3]) : "r"(a));
}
__device__ __forceinline__ void ldsm_x2(uint32_t a, uint32_t* r) {
    asm volatile("ldmatrix.sync.aligned.m8n8.x2.shared.b16 {%0,%1}, [%2];"
                 : "=r"(r[0]), "=r"(r[1]) : "r"(a));
}
__device__ __forceinline__ void mma_f16(float* d, const uint32_t* a, uint32_t b0, uint32_t b1) {
    asm volatile("mma.sync.aligned.m16n8k16.row.col.f32.f16.f16.f32 "
        "{%0,%1,%2,%3}, {%4,%5,%6,%7}, {%8,%9}, {%0,%1,%2,%3};"
        : "+f"(d[0]), "+f"(d[1]), "+f"(d[2]), "+f"(d[3])
        : "r"(a[0]), "r"(a[1]), "r"(a[2]), "r"(a[3]), "r"(b0), "r"(b1));
}

// ---------------- prep: feat -> padded fp16 plane [flat][96] -----------------
__global__ __launch_bounds__(128) void split_feat_kernel(const float* __restrict__ feat)
{
    int flat = blockIdx.x * 128 + threadIdx.x;
    if (flat >= NPX) return;
    int xp = flat % Wp, yp = (flat / Wp) % Hp, n = flat / (Hp * Wp);
    bool interior = (yp >= 1 && yp <= cH && xp >= 1 && xp <= cW);
    __half* dh = g_A1 + (size_t)flat * CIN1;
    #pragma unroll
    for (int c = 0; c < 3; c++) {
        uint32_t hw[16];
        if (interior) {
            const float* src = feat + ((size_t)(n * CIN1 + c * 32) * cH + (yp - 1)) * cW + (xp - 1);
            #pragma unroll
            for (int i = 0; i < 16; i++) {
                __half2 h = __floats2half2_rn(src[(size_t)(2 * i) * HW],
                                              src[(size_t)(2 * i + 1) * HW]);
                hw[i] = *reinterpret_cast<uint32_t*>(&h);
            }
        } else {
            #pragma unroll
            for (int i = 0; i < 16; i++) hw[i] = 0;
        }
        #pragma unroll
        for (int j = 0; j < 4; j++)
            *reinterpret_cast<uint4*>(dh + c * 32 + j * 8) = *reinterpret_cast<uint4*>(hw + j * 4);
    }
}

__global__ __launch_bounds__(128) void halo2_kernel()
{
    int flat = blockIdx.x * 128 + threadIdx.x;
    if (flat >= NPX) return;
    int xp = flat % Wp, yp = (flat / Wp) % Hp;
    if (yp >= 1 && yp <= cH && xp >= 1 && xp <= cW) return;
    uint4 z = {0, 0, 0, 0};
    uint4* dh = reinterpret_cast<uint4*>(g_A2 + (size_t)flat * CIN2);
    #pragma unroll
    for (int j = 0; j < 16; j++) dh[j] = z;
}

// weights OIHW fp32 -> [pos][chunk][co][32] fp16
template<int CIN, int NCO>
__global__ __launch_bounds__(256) void split_w_kernel(const float* __restrict__ wt,
                                                      __half* __restrict__ out)
{
    constexpr int NCH = CIN / 32;
    int idx = blockIdx.x * 256 + threadIdx.x;
    if (idx >= 9 * NCH * NCO * 32) return;
    int k = idx & 31; int t = idx >> 5;
    int co = t % NCO; t /= NCO;
    int chunk = t % NCH;
    int pos = t / NCH;
    out[idx] = __float2half(wt[((size_t)co * CIN + chunk * 32 + k) * 9 + pos]);
}

// ---------------- HMMA fp16 conv: CTA = 128px x NCO, 8 warps (4M x 2N) -------
template<int CIN, int NCO, bool EPI1>
__global__ __launch_bounds__(256, 2) void conv_mma_kernel(
    const __half* __restrict__ Ap, const __half* __restrict__ Wv,
    const float* __restrict__ bias, float* __restrict__ maskOut)
{
    constexpr int NCH = CIN / 32;
    constexpr int R   = 9 * NCH;               // rounds (pos x chunk)
    constexpr int WN  = NCO / 2;                // co per warp-N group
    constexpr int NT  = NCO / 16;               // n-tiles per warp (8 / 9)
    constexpr int NPAIR = NT / 2;
    constexpr int AB  = 128 * 80;               // A buffer (padded 80B rows)
    constexpr int SB  = AB + NCO * 80;          // full round buffer

    extern __shared__ __align__(16) char smem[];
    const uint32_t s0 = smem_u32(smem);

    const int tid = threadIdx.x, lane = tid & 31, wid = tid >> 5;
    const int warpM = wid & 3, warpN = wid >> 2;
    const int gr = lane >> 2;

    // ldmatrix per-lane address offsets (80B-padded rows; conflict-free)
    const uint32_t aoff = (uint32_t)((lane & 15) * 80 + (lane >> 4) * 16);
    const uint32_t boff = (uint32_t)((((lane >> 4) << 3) + (lane & 7)) * 80 + ((lane >> 3) & 1) * 16);
    const uint32_t boff2 = (uint32_t)((lane & 7) * 80 + ((lane >> 3) & 1) * 16);

    const int x0 = blockIdx.x * 128, y = blockIdx.y, n = blockIdx.z;

    float acc[2][NT][4];
    #pragma unroll
    for (int mi = 0; mi < 2; mi++)
        #pragma unroll
        for (int ni = 0; ni < NT; ni++)
            #pragma unroll
            for (int j = 0; j < 4; j++) acc[mi][ni][j] = 0.0f;

    auto issue = [&](int r, int buf) {
        const int pos = r / NCH, chunk = r - pos * NCH;
        const int ky = pos / 3, kx = pos - ky * 3;
        const size_t fb = ((size_t)(n * Hp) + y + ky) * Wp + x0 + kx;
        const uint32_t sb = s0 + buf * SB;
        // A: 128 rows x 32 k (64B each) -> 512 x 16B
        #pragma unroll
        for (int i = 0; i < 2; i++) {
            int idx = i * 256 + tid;
            int rr = idx >> 2, j = idx & 3;
            const __half* src = Ap + (fb + rr) * CIN + chunk * 32 + j * 8;
            cpa16(sb + rr * 80 + j * 16, src);
        }
        // W: NCO rows x 64B
        const __half* ws = Wv + (size_t)(pos * NCH + chunk) * NCO * 32;
        for (int idx = tid; idx < NCO * 4; idx += 256) {
            int rr = idx >> 2, j = idx & 3;
            cpa16(sb + AB + rr * 80 + j * 16, ws + rr * 32 + j * 8);
        }
        asm volatile("cp.async.commit_group;" ::: "memory");
    };

    auto compute = [&](int buf) {
        const uint32_t sb  = s0 + buf * SB;
        const uint32_t Wb  = sb + AB;
        #pragma unroll
        for (int kh = 0; kh < 2; kh++) {
            const uint32_t ko = kh * 32;
            uint32_t a[2][4];
            #pragma unroll
            for (int mi = 0; mi < 2; mi++) {
                const uint32_t ab = (uint32_t)((warpM * 32 + mi * 16) * 80) + aoff + ko;
                ldsm_x4(sb + ab, a[mi]);
            }
            #pragma unroll
            for (int np = 0; np < NPAIR; np++) {
                const uint32_t nb = (uint32_t)((warpN * WN + np * 16) * 80) + boff + ko;
                uint32_t w[4];
                ldsm_x4(Wb + nb, w);
                #pragma unroll
                for (int mi = 0; mi < 2; mi++) {
                    mma_f16(acc[mi][2 * np],     a[mi], w[0], w[1]);
                    mma_f16(acc[mi][2 * np + 1], a[mi], w[2], w[3]);
                }
            }
            if (NT & 1) {   // odd tail tile (conv2: NT=9)
                const uint32_t nb = (uint32_t)((warpN * WN + (NT - 1) * 8) * 80) + boff2 + ko;
                uint32_t w[2];
                ldsm_x2(Wb + nb, w);
                #pragma unroll
                for (int mi = 0; mi < 2; mi++)
                    mma_f16(acc[mi][NT - 1], a[mi], w[0], w[1]);
            }
        }
    };

    issue(0, 0);
    for (int r = 0; r < R; r++) {
        if (r + 1 < R) {
            issue(r + 1, (r + 1) & 1);
            asm volatile("cp.async.wait_group 1;" ::: "memory");
        } else {
            asm volatile("cp.async.wait_group 0;" ::: "memory");
        }
        __syncthreads();
        compute(r & 1);
        __syncthreads();
    }

    // ---------------- epilogue ----------------
    const int t2 = (lane & 3) * 2;
    #pragma unroll
    for (int mi = 0; mi < 2; mi++) {
        #pragma unroll
        for (int rr = 0; rr < 2; rr++) {
            const int px = x0 + warpM * 32 + mi * 16 + gr + rr * 8;   // global x
            if (EPI1) {
                const size_t flat = ((size_t)(n * Hp) + y + 1) * Wp + px + 1;
                __half* dh = g_A2 + flat * CIN2;
                #pragma unroll
                for (int ni = 0; ni < NT; ni++) {
                    const int co = warpN * WN + ni * 8 + t2;
                    float v0 = acc[mi][ni][rr * 2 + 0] + __ldg(bias + co);
                    float v1 = acc[mi][ni][rr * 2 + 1] + __ldg(bias + co + 1);
                    v0 = v0 > 0.f ? v0 : 0.1f * v0;
                    v1 = v1 > 0.f ? v1 : 0.1f * v1;
                    __half2 h = __floats2half2_rn(v0, v1);
                    *reinterpret_cast<uint32_t*>(dh + co) = *reinterpret_cast<uint32_t*>(&h);
                }
            } else {
                #pragma unroll
                for (int ni = 0; ni < NT; ni++) {
                    const int co = warpN * WN + ni * 8 + t2;
                    float v0 = acc[mi][ni][rr * 2 + 0] + __ldg(bias + co);
                    float v1 = acc[mi][ni][rr * 2 + 1] + __ldg(bias + co + 1);
                    size_t o = ((size_t)(n * COUT2 + co) * cH + y) * cW + px;
                    maskOut[o]      = v0;
                    maskOut[o + HW] = v1;
                }
            }
        }
    }
}

// ---------------- softmax + convex upsample + pixel shuffle -----------------
__global__ __launch_bounds__(256)
void upsample_kernel(const float* __restrict__ flow,
                     const float* __restrict__ mask, float* __restrict__ out)
{
    const int idx = blockIdx.x * blockDim.x + threadIdx.x;
    if (idx >= cN * HW) return;
    const int x = idx % cW, y = (idx / cW) % cH, n = idx / HW;

    float fpx[9], fpy[9];
    #pragma unroll
    for (int ki = 0; ki < 3; ki++)
        #pragma unroll
        for (int kj = 0; kj < 3; kj++) {
            const int k = ki * 3 + kj;
            const int yy = y + ki - 1, xx = x + kj - 1;
            const bool ok = (unsigned)yy < (unsigned)cH && (unsigned)xx < (unsigned)cW;
            fpx[k] = ok ? 4.0f * flow[(n * 2 + 0) * HW + yy * cW + xx] : 0.0f;
            fpy[k] = ok ? 4.0f * flow[(n * 2 + 1) * HW + yy * cW + xx] : 0.0f;
        }
    const size_t base = (size_t)n * COUT2 * HW + y * cW + x;
    const int OH = 4 * cH, OW = 4 * cW;
    #pragma unroll
    for (int a = 0; a < 4; a++)
        #pragma unroll
        for (int b = 0; b < 4; b++) {
            float m[9], mx = -1e30f;
            #pragma unroll
            for (int k = 0; k < 9; k++) {
                m[k] = 0.25f * mask[base + (size_t)(k * 16 + a * 4 + b) * HW];
                mx = fmaxf(mx, m[k]);
            }
            float s = 0.0f;
            #pragma unroll
            for (int k = 0; k < 9; k++) { m[k] = __expf(m[k] - mx); s += m[k]; }
            const float inv = 1.0f / s;
            float ox = 0.0f, oy = 0.0f;
            #pragma unroll
            for (int k = 0; k < 9; k++) { ox += m[k] * fpx[k]; oy += m[k] * fpy[k]; }
            const int oyi = y * 4 + a, oxi = x * 4 + b;
            out[((size_t)(n * 2 + 0) * OH + oyi) * OW + oxi] = ox * inv;
            out[((size_t)(n * 2 + 1) * OH + oyi) * OW + oxi] = oy * inv;
        }
}

// ---------------------------------------------------------------------------
extern "C" void kernel_launch(void* const* d_in, const int* in_sizes, int n_in,
                              void* d_out, int out_size)
{
    (void)in_sizes; (void)n_in; (void)out_size;
    const float* flow = (const float*)d_in[0];
    const float* feat = (const float*)d_in[1];
    const float* w1   = (const float*)d_in[2];
    const float* b1   = (const float*)d_in[3];
    const float* w2   = (const float*)d_in[4];
    const float* b2   = (const float*)d_in[5];
    float* out = (float*)d_out;

    __half *a1, *a2, *w1s, *w2s; float* msk;
    cudaGetSymbolAddress((void**)&a1,  g_A1);
    cudaGetSymbolAddress((void**)&a2,  g_A2);
    cudaGetSymbolAddress((void**)&w1s, g_W1);
    cudaGetSymbolAddress((void**)&w2s, g_W2);
    cudaGetSymbolAddress((void**)&msk, g_mask);

    constexpr int SM1 = 2 * (128 * 80 + COUT1 * 80);   // 40,960
    constexpr int SM2 = 2 * (128 * 80 + COUT2 * 80);   // 43,520
    cudaFuncSetAttribute(conv_mma_kernel<CIN1, COUT1, true>,
                         cudaFuncAttributeMaxDynamicSharedMemorySize, SM1);
    cudaFuncSetAttribute(conv_mma_kernel<CIN2, COUT2, false>,
                         cudaFuncAttributeMaxDynamicSharedMemorySize, SM2);

    split_feat_kernel<<<(NPX + 127) / 128, 128>>>(feat);
    halo2_kernel<<<(NPX + 127) / 128, 128>>>();
    split_w_kernel<CIN1, COUT1><<<(9 * 3 * COUT1 * 32 + 255) / 256, 256>>>(w1, w1s);
    split_w_kernel<CIN2, COUT2><<<(9 * 4 * COUT2 * 32 + 255) / 256, 256>>>(w2, w2s);

    conv_mma_kernel<CIN1, COUT1, true ><<<dim3(2, cH, cN), 256, SM1>>>(a1, w1s, b1, msk);
    conv_mma_kernel<CIN2, COUT2, false><<<dim3(2, cH, cN), 256, SM2>>>(a2, w2s, b2, msk);

    upsample_kernel<<<(cN * HW + 255) / 256, 256>>>(flow, msk, out);
}

// round 13
// speedup vs baseline: 2.6511x; 1.0955x over previous
#include <cuda_runtime.h>
#include <cuda_fp16.h>
#include <cstdint>
#include <math.h>

constexpr int cN = 4, cH = 128, cW = 256;
constexpr int CIN1 = 96,  COUT1 = 128;
constexpr int CIN2 = 128, COUT2 = 144;
constexpr int HW = cH * cW, Hp = cH + 2, Wp = cW + 2;
constexpr int NPX = cN * Hp * Wp;

// Static scratch (16B-aligned for cp.async / uint4)
__device__ __align__(256) __half g_A1[(size_t)NPX * CIN1];
__device__ __align__(256) __half g_A2[(size_t)NPX * CIN2];
__device__ __align__(256) __half g_W1[9 * COUT1 * CIN1];   // [pos][co][cin]
__device__ __align__(256) __half g_W2[9 * COUT2 * CIN2];

// ---------------- helpers ----------------------------------------------------
__device__ __forceinline__ uint32_t smem_u32(const void* p) {
    uint32_t a;
    asm("{ .reg .u64 t; cvta.to.shared.u64 t, %1; cvt.u32.u64 %0, t; }" : "=r"(a) : "l"(p));
    return a;
}
__device__ __forceinline__ void cpa16(uint32_t s, const void* g) {
    asm volatile("cp.async.cg.shared.global [%0], [%1], 16;" :: "r"(s), "l"(g) : "memory");
}
__device__ __forceinline__ void ldsm_x4(uint32_t a, uint32_t* r) {
    asm volatile("ldmatrix.sync.aligned.m8n8.x4.shared.b16 {%0,%1,%2,%3}, [%4];"
                 : "=r"(r[0]), "=r"(r[1]), "=r"(r[2]), "=r"(r[3]) : "r"(a));
}
__device__ __forceinline__ void ldsm_x2(uint32_t a, uint32_t* r) {
    asm volatile("ldmatrix.sync.aligned.m8n8.x2.shared.b16 {%0,%1}, [%2];"
                 : "=r"(r[0]), "=r"(r[1]) : "r"(a));
}
__device__ __forceinline__ void mma_f16(float* d, const uint32_t* a, uint32_t b0, uint32_t b1) {
    asm volatile("mma.sync.aligned.m16n8k16.row.col.f32.f16.f16.f32 "
        "{%0,%1,%2,%3}, {%4,%5,%6,%7}, {%8,%9}, {%0,%1,%2,%3};"
        : "+f"(d[0]), "+f"(d[1]), "+f"(d[2]), "+f"(d[3])
        : "r"(a[0]), "r"(a[1]), "r"(a[2]), "r"(a[3]), "r"(b0), "r"(b1));
}

// ---------------- prep: feat -> padded fp16 plane [flat][96] -----------------
__global__ __launch_bounds__(128) void split_feat_kernel(const float* __restrict__ feat)
{
    int flat = blockIdx.x * 128 + threadIdx.x;
    if (flat >= NPX) return;
    int xp = flat % Wp, yp = (flat / Wp) % Hp, n = flat / (Hp * Wp);
    bool interior = (yp >= 1 && yp <= cH && xp >= 1 && xp <= cW);
    __half* dh = g_A1 + (size_t)flat * CIN1;
    #pragma unroll
    for (int c = 0; c < 3; c++) {
        uint32_t hw[16];
        if (interior) {
            const float* src = feat + ((size_t)(n * CIN1 + c * 32) * cH + (yp - 1)) * cW + (xp - 1);
            #pragma unroll
            for (int i = 0; i < 16; i++) {
                __half2 h = __floats2half2_rn(src[(size_t)(2 * i) * HW],
                                              src[(size_t)(2 * i + 1) * HW]);
                hw[i] = *reinterpret_cast<uint32_t*>(&h);
            }
        } else {
            #pragma unroll
            for (int i = 0; i < 16; i++) hw[i] = 0;
        }
        #pragma unroll
        for (int j = 0; j < 4; j++)
            *reinterpret_cast<uint4*>(dh + c * 32 + j * 8) = *reinterpret_cast<uint4*>(hw + j * 4);
    }
}

__global__ __launch_bounds__(128) void halo2_kernel()
{
    int flat = blockIdx.x * 128 + threadIdx.x;
    if (flat >= NPX) return;
    int xp = flat % Wp, yp = (flat / Wp) % Hp;
    if (yp >= 1 && yp <= cH && xp >= 1 && xp <= cW) return;
    uint4 z = {0, 0, 0, 0};
    uint4* dh = reinterpret_cast<uint4*>(g_A2 + (size_t)flat * CIN2);
    #pragma unroll
    for (int j = 0; j < 16; j++) dh[j] = z;
}

// weights OIHW fp32 -> [pos][co][cin] fp16 (K-major rows)
template<int CIN, int NCO>
__global__ __launch_bounds__(256) void split_w_kernel(const float* __restrict__ wt,
                                                      __half* __restrict__ out)
{
    int idx = blockIdx.x * 256 + threadIdx.x;
    if (idx >= 9 * NCO * CIN) return;
    int ci = idx % CIN; int t = idx / CIN;
    int co = t % NCO;
    int pos = t / NCO;
    out[idx] = __float2half(wt[((size_t)co * CIN + ci) * 9 + pos]);
}

// ---------------- HMMA fp16 conv: CTA = 128px x NCO, 8 warps (4M x 2N) -------
// KR = K-depth per round (96 conv1, 64 conv2). Pitch P = KR*2+16 is ldmatrix
// conflict-free (bank-walk distinct per 8 rows for both 208 and 144).
// EPI1: write fp16 plane for conv2. Else: fused softmax+upsample epilogue.
template<int CIN, int NCO, int KR, bool EPI1>
__global__ __launch_bounds__(256, 2) void conv_mma_kernel(
    const __half* __restrict__ Ap, const __half* __restrict__ Wv,
    const float* __restrict__ bias,
    const float* __restrict__ flow, float* __restrict__ out)
{
    constexpr int NKC = CIN / KR;               // k-chunks per position
    constexpr int R   = 9 * NKC;                // rounds
    constexpr int NKH = KR / 16;                // kh steps per round
    constexpr int A16 = KR / 8;                 // 16B segments per row
    constexpr int P   = KR * 2 + 16;            // smem row pitch (bytes)
    constexpr int WN  = NCO / 2;                // co per warp-N group
    constexpr int NT  = NCO / 16;               // n-tiles per warp (8 / 9)
    constexpr int NPAIR = NT / 2;
    constexpr int AB  = 128 * P;
    constexpr int SB  = AB + NCO * P;

    extern __shared__ __align__(16) char smem[];
    const uint32_t s0 = smem_u32(smem);

    const int tid = threadIdx.x, lane = tid & 31, wid = tid >> 5;
    const int warpM = wid & 3, warpN = wid >> 2;
    const int gr = lane >> 2;

    const uint32_t aoff = (uint32_t)((lane & 15) * P + (lane >> 4) * 16);
    const uint32_t boff = (uint32_t)((((lane >> 4) << 3) + (lane & 7)) * P + ((lane >> 3) & 1) * 16);
    const uint32_t boff2 = (uint32_t)((lane & 7) * P + ((lane >> 3) & 1) * 16);

    const int x0 = blockIdx.x * 128, y = blockIdx.y, n = blockIdx.z;

    float acc[2][NT][4];
    #pragma unroll
    for (int mi = 0; mi < 2; mi++)
        #pragma unroll
        for (int ni = 0; ni < NT; ni++)
            #pragma unroll
            for (int j = 0; j < 4; j++) acc[mi][ni][j] = 0.0f;

    auto issue = [&](int r, int buf) {
        const int pos = r / NKC, kc = r % NKC;
        const int ky = pos / 3, kx = pos - ky * 3;
        const size_t fb = ((size_t)(n * Hp) + y + ky) * Wp + x0 + kx;
        const uint32_t sb = s0 + buf * SB;
        #pragma unroll
        for (int idx = tid; idx < 128 * A16; idx += 256) {
            int rr = idx / A16, j = idx % A16;
            cpa16(sb + rr * P + j * 16, Ap + (fb + rr) * CIN + kc * KR + j * 8);
        }
        const __half* ws = Wv + (size_t)pos * NCO * CIN + kc * KR;
        #pragma unroll
        for (int idx = tid; idx < NCO * A16; idx += 256) {
            int rr = idx / A16, j = idx % A16;
            cpa16(sb + AB + rr * P + j * 16, ws + (size_t)rr * CIN + j * 8);
        }
        asm volatile("cp.async.commit_group;" ::: "memory");
    };

    auto compute = [&](int buf) {
        const uint32_t sb = s0 + buf * SB;
        const uint32_t Wb = sb + AB;
        #pragma unroll
        for (int kh = 0; kh < NKH; kh++) {
            const uint32_t ko = kh * 32;
            uint32_t a[2][4];
            #pragma unroll
            for (int mi = 0; mi < 2; mi++)
                ldsm_x4(sb + (uint32_t)((warpM * 32 + mi * 16) * P) + aoff + ko, a[mi]);
            #pragma unroll
            for (int np = 0; np < NPAIR; np++) {
                uint32_t w[4];
                ldsm_x4(Wb + (uint32_t)((warpN * WN + np * 16) * P) + boff + ko, w);
                #pragma unroll
                for (int mi = 0; mi < 2; mi++) {
                    mma_f16(acc[mi][2 * np],     a[mi], w[0], w[1]);
                    mma_f16(acc[mi][2 * np + 1], a[mi], w[2], w[3]);
                }
            }
            if (NT & 1) {
                uint32_t w[2];
                ldsm_x2(Wb + (uint32_t)((warpN * WN + (NT - 1) * 8) * P) + boff2 + ko, w);
                #pragma unroll
                for (int mi = 0; mi < 2; mi++)
                    mma_f16(acc[mi][NT - 1], a[mi], w[0], w[1]);
            }
        }
    };

    issue(0, 0);
    for (int r = 0; r < R; r++) {
        if (r + 1 < R) {
            issue(r + 1, (r + 1) & 1);
            asm volatile("cp.async.wait_group 1;" ::: "memory");
        } else {
            asm volatile("cp.async.wait_group 0;" ::: "memory");
        }
        __syncthreads();
        compute(r & 1);
        __syncthreads();
    }

    const int t2 = (lane & 3) * 2;

    if (EPI1) {
        // write fp16 padded plane for conv2
        #pragma unroll
        for (int mi = 0; mi < 2; mi++) {
            #pragma unroll
            for (int rr = 0; rr < 2; rr++) {
                const int px = x0 + warpM * 32 + mi * 16 + gr + rr * 8;
                const size_t flat = ((size_t)(n * Hp) + y + 1) * Wp + px + 1;
                __half* dh = g_A2 + flat * CIN2;
                #pragma unroll
                for (int ni = 0; ni < NT; ni++) {
                    const int co = warpN * WN + ni * 8 + t2;
                    float v0 = acc[mi][ni][rr * 2 + 0] + __ldg(bias + co);
                    float v1 = acc[mi][ni][rr * 2 + 1] + __ldg(bias + co + 1);
                    v0 = v0 > 0.f ? v0 : 0.1f * v0;
                    v1 = v1 > 0.f ? v1 : 0.1f * v1;
                    __half2 h = __floats2half2_rn(v0, v1);
                    *reinterpret_cast<uint32_t*>(dh + co) = *reinterpret_cast<uint32_t*>(&h);
                }
            }
        }
    } else {
        // ---- fused softmax + convex upsample + pixel shuffle ----
        float* sm = reinterpret_cast<float*>(smem);   // [128 px][145 pitch]
        __syncthreads();   // all rounds done reading smem buffers
        #pragma unroll
        for (int mi = 0; mi < 2; mi++)
            #pragma unroll
            for (int rr = 0; rr < 2; rr++) {
                const int pxl = warpM * 32 + mi * 16 + gr + rr * 8;
                #pragma unroll
                for (int ni = 0; ni < NT; ni++) {
                    const int co = warpN * WN + ni * 8 + t2;
                    sm[pxl * 145 + co]     = acc[mi][ni][rr * 2 + 0] + __ldg(bias + co);
                    sm[pxl * 145 + co + 1] = acc[mi][ni][rr * 2 + 1] + __ldg(bias + co + 1);
                }
            }
        __syncthreads();

        const int pxl = tid >> 1, bh = tid & 1;
        const int x = x0 + pxl;

        float fpx[9], fpy[9];
        #pragma unroll
        for (int ki = 0; ki < 3; ki++)
            #pragma unroll
            for (int kj = 0; kj < 3; kj++) {
                const int k = ki * 3 + kj;
                const int yy = y + ki - 1, xx = x + kj - 1;
                const bool ok = (unsigned)yy < (unsigned)cH && (unsigned)xx < (unsigned)cW;
                fpx[k] = ok ? 4.0f * __ldg(flow + (size_t)(n * 2 + 0) * HW + yy * cW + xx) : 0.0f;
                fpy[k] = ok ? 4.0f * __ldg(flow + (size_t)(n * 2 + 1) * HW + yy * cW + xx) : 0.0f;
            }

        const int OH = 4 * cH, OW = 4 * cW;
        #pragma unroll
        for (int a = 0; a < 4; a++) {
            #pragma unroll
            for (int b2 = 0; b2 < 2; b2++) {
                const int b = bh * 2 + b2;
                float m[9], mx = -1e30f;
                #pragma unroll
                for (int k = 0; k < 9; k++) {
                    m[k] = 0.25f * sm[pxl * 145 + k * 16 + a * 4 + b];
                    mx = fmaxf(mx, m[k]);
                }
                float s = 0.0f;
                #pragma unroll
                for (int k = 0; k < 9; k++) { m[k] = __expf(m[k] - mx); s += m[k]; }
                const float inv = 1.0f / s;
                float ox = 0.0f, oy = 0.0f;
                #pragma unroll
                for (int k = 0; k < 9; k++) { ox += m[k] * fpx[k]; oy += m[k] * fpy[k]; }
                const int oyi = y * 4 + a, oxi = x * 4 + b;
                out[((size_t)(n * 2 + 0) * OH + oyi) * OW + oxi] = ox * inv;
                out[((size_t)(n * 2 + 1) * OH + oyi) * OW + oxi] = oy * inv;
            }
        }
    }
}

// ---------------------------------------------------------------------------
extern "C" void kernel_launch(void* const* d_in, const int* in_sizes, int n_in,
                              void* d_out, int out_size)
{
    (void)in_sizes; (void)n_in; (void)out_size;
    const float* flow = (const float*)d_in[0];
    const float* feat = (const float*)d_in[1];
    const float* w1   = (const float*)d_in[2];
    const float* b1   = (const float*)d_in[3];
    const float* w2   = (const float*)d_in[4];
    const float* b2   = (const float*)d_in[5];
    float* out = (float*)d_out;

    __half *a1, *a2, *w1s, *w2s;
    cudaGetSymbolAddress((void**)&a1,  g_A1);
    cudaGetSymbolAddress((void**)&a2,  g_A2);
    cudaGetSymbolAddress((void**)&w1s, g_W1);
    cudaGetSymbolAddress((void**)&w2s, g_W2);

    // conv1: KR=96 (full CIN), P=208: smem = 2*(128+128)*208 = 106,496
    constexpr int SM1 = 2 * ((128 + COUT1) * (96 * 2 + 16));
    // conv2: KR=64, P=144: smem = 2*(128+144)*144 = 78,336 (>= 74,240 epi)
    constexpr int SM2 = 2 * ((128 + COUT2) * (64 * 2 + 16));
    static_assert(SM2 >= 128 * 145 * 4, "epilogue smem");

    cudaFuncSetAttribute(conv_mma_kernel<CIN1, COUT1, 96, true>,
                         cudaFuncAttributeMaxDynamicSharedMemorySize, SM1);
    cudaFuncSetAttribute(conv_mma_kernel<CIN2, COUT2, 64, false>,
                         cudaFuncAttributeMaxDynamicSharedMemorySize, SM2);

    split_feat_kernel<<<(NPX + 127) / 128, 128>>>(feat);
    halo2_kernel<<<(NPX + 127) / 128, 128>>>();
    split_w_kernel<CIN1, COUT1><<<(9 * COUT1 * CIN1 + 255) / 256, 256>>>(w1, w1s);
    split_w_kernel<CIN2, COUT2><<<(9 * COUT2 * CIN2 + 255) / 256, 256>>>(w2, w2s);

    conv_mma_kernel<CIN1, COUT1, 96, true ><<<dim3(2, cH, cN), 256, SM1>>>(
        a1, w1s, b1, nullptr, nullptr);
    conv_mma_kernel<CIN2, COUT2, 64, false><<<dim3(2, cH, cN), 256, SM2>>>(
        a2, w2s, b2, flow, out);
}

// round 14
// speedup vs baseline: 2.8141x; 1.0615x over previous
#include <cuda_runtime.h>
#include <cuda_fp16.h>
#include <cstdint>
#include <math.h>

constexpr int cN = 4, cH = 128, cW = 256;
constexpr int CIN1 = 96,  COUT1 = 128;
constexpr int CIN2 = 128, COUT2 = 144;
constexpr int HW = cH * cW, Hp = cH + 2, Wp = cW + 2;
constexpr int NPX = cN * Hp * Wp;

// Static scratch (16B-aligned for cp.async / uint4)
__device__ __align__(256) __half g_A1[(size_t)NPX * CIN1];
__device__ __align__(256) __half g_A2[(size_t)NPX * CIN2];
__device__ __align__(256) __half g_W1[9 * COUT1 * CIN1];   // [pos][co][cin]
__device__ __align__(256) __half g_W2[9 * COUT2 * CIN2];

// ---------------- helpers ----------------------------------------------------
__device__ __forceinline__ uint32_t smem_u32(const void* p) {
    uint32_t a;
    asm("{ .reg .u64 t; cvta.to.shared.u64 t, %1; cvt.u32.u64 %0, t; }" : "=r"(a) : "l"(p));
    return a;
}
__device__ __forceinline__ void cpa16(uint32_t s, const void* g) {
    asm volatile("cp.async.cg.shared.global [%0], [%1], 16;" :: "r"(s), "l"(g) : "memory");
}
__device__ __forceinline__ void ldsm_x4(uint32_t a, uint32_t* r) {
    asm volatile("ldmatrix.sync.aligned.m8n8.x4.shared.b16 {%0,%1,%2,%3}, [%4];"
                 : "=r"(r[0]), "=r"(r[1]), "=r"(r[2]), "=r"(r[3]) : "r"(a));
}
__device__ __forceinline__ void ldsm_x2(uint32_t a, uint32_t* r) {
    asm volatile("ldmatrix.sync.aligned.m8n8.x2.shared.b16 {%0,%1}, [%2];"
                 : "=r"(r[0]), "=r"(r[1]) : "r"(a));
}
__device__ __forceinline__ void mma_f16(float* d, const uint32_t* a, uint32_t b0, uint32_t b1) {
    asm volatile("mma.sync.aligned.m16n8k16.row.col.f32.f16.f16.f32 "
        "{%0,%1,%2,%3}, {%4,%5,%6,%7}, {%8,%9}, {%0,%1,%2,%3};"
        : "+f"(d[0]), "+f"(d[1]), "+f"(d[2]), "+f"(d[3])
        : "r"(a[0]), "r"(a[1]), "r"(a[2]), "r"(a[3]), "r"(b0), "r"(b1));
}

// ---------------- prep: feat -> padded fp16 plane [flat][96] -----------------
__global__ __launch_bounds__(128) void split_feat_kernel(const float* __restrict__ feat)
{
    int flat = blockIdx.x * 128 + threadIdx.x;
    if (flat >= NPX) return;
    int xp = flat % Wp, yp = (flat / Wp) % Hp, n = flat / (Hp * Wp);
    bool interior = (yp >= 1 && yp <= cH && xp >= 1 && xp <= cW);
    __half* dh = g_A1 + (size_t)flat * CIN1;
    #pragma unroll
    for (int c = 0; c < 3; c++) {
        uint32_t hw[16];
        if (interior) {
            const float* src = feat + ((size_t)(n * CIN1 + c * 32) * cH + (yp - 1)) * cW + (xp - 1);
            #pragma unroll
            for (int i = 0; i < 16; i++) {
                __half2 h = __floats2half2_rn(src[(size_t)(2 * i) * HW],
                                              src[(size_t)(2 * i + 1) * HW]);
                hw[i] = *reinterpret_cast<uint32_t*>(&h);
            }
        } else {
            #pragma unroll
            for (int i = 0; i < 16; i++) hw[i] = 0;
        }
        #pragma unroll
        for (int j = 0; j < 4; j++)
            *reinterpret_cast<uint4*>(dh + c * 32 + j * 8) = *reinterpret_cast<uint4*>(hw + j * 4);
    }
}

__global__ __launch_bounds__(128) void halo2_kernel()
{
    int flat = blockIdx.x * 128 + threadIdx.x;
    if (flat >= NPX) return;
    int xp = flat % Wp, yp = (flat / Wp) % Hp;
    if (yp >= 1 && yp <= cH && xp >= 1 && xp <= cW) return;
    uint4 z = {0, 0, 0, 0};
    uint4* dh = reinterpret_cast<uint4*>(g_A2 + (size_t)flat * CIN2);
    #pragma unroll
    for (int j = 0; j < 16; j++) dh[j] = z;
}

// weights OIHW fp32 -> [pos][co][cin] fp16 (K-major rows)
template<int CIN, int NCO>
__global__ __launch_bounds__(256) void split_w_kernel(const float* __restrict__ wt,
                                                      __half* __restrict__ out)
{
    int idx = blockIdx.x * 256 + threadIdx.x;
    if (idx >= 9 * NCO * CIN) return;
    int ci = idx % CIN; int t = idx / CIN;
    int co = t % NCO;
    int pos = t / NCO;
    out[idx] = __float2half(wt[((size_t)co * CIN + ci) * 9 + pos]);
}

// ---------------- HMMA fp16 conv: CTA = 128px x NCO, 8 warps (4M x 2N) -------
// A-chunk-stationary: per K-chunk, stage the 3-row x 130-px halo window ONCE
// (single buffer); each of the 9 positions reads it with a (ky*130+kx) row
// shift — pitch P keeps ldmatrix conflict-free under uniform row shifts.
// W double-buffered per position. EPI1: write fp16 plane for conv2;
// else: fused softmax + convex upsample + pixel-shuffle epilogue.
template<int CIN, int NCO, int KR, bool EPI1>
__global__ __launch_bounds__(256, 2) void conv_mma_kernel(
    const __half* __restrict__ Ap, const __half* __restrict__ Wv,
    const float* __restrict__ bias,
    const float* __restrict__ flow, float* __restrict__ out)
{
    constexpr int NKC = CIN / KR;               // k-chunks
    constexpr int NKH = KR / 16;                // kh steps per position
    constexpr int A16 = KR / 8;                 // 16B segments per row
    constexpr int P   = KR * 2 + 16;            // smem row pitch (bytes)
    constexpr int AROWS = 3 * 130;              // staged A rows per chunk
    constexpr int WN  = NCO / 2;                // co per warp-N group
    constexpr int NT  = NCO / 16;               // n-tiles per warp (8 / 9)
    constexpr int NPAIR = NT / 2;
    constexpr int ABUF = AROWS * P;
    constexpr int WBUF = NCO * P;

    extern __shared__ __align__(16) char smem[];
    const uint32_t sA = smem_u32(smem);
    const uint32_t sW = sA + ABUF;

    const int tid = threadIdx.x, lane = tid & 31, wid = tid >> 5;
    const int warpM = wid & 3, warpN = wid >> 2;
    const int gr = lane >> 2;

    const uint32_t aoff = (uint32_t)((lane & 15) * P + (lane >> 4) * 16);
    const uint32_t boff = (uint32_t)((((lane >> 4) << 3) + (lane & 7)) * P + ((lane >> 3) & 1) * 16);
    const uint32_t boff2 = (uint32_t)((lane & 7) * P + ((lane >> 3) & 1) * 16);

    const int x0 = blockIdx.x * 128, y = blockIdx.y, n = blockIdx.z;

    float acc[2][NT][4];
    #pragma unroll
    for (int mi = 0; mi < 2; mi++)
        #pragma unroll
        for (int ni = 0; ni < NT; ni++)
            #pragma unroll
            for (int j = 0; j < 4; j++) acc[mi][ni][j] = 0.0f;

    auto stageA = [&](int kc) {
        const size_t rowb = (size_t)(n * Hp + y) * Wp + x0;
        for (int idx = tid; idx < AROWS * A16; idx += 256) {
            int rr = idx / A16, j = idx % A16;
            int ky = rr / 130, px = rr - ky * 130;
            cpa16(sA + rr * P + j * 16,
                  Ap + (rowb + (size_t)ky * Wp + px) * CIN + kc * KR + j * 8);
        }
    };
    auto stageW = [&](int pos, int kc, int buf) {
        const __half* ws = Wv + (size_t)pos * NCO * CIN + kc * KR;
        for (int idx = tid; idx < NCO * A16; idx += 256) {
            int rr = idx / A16, j = idx % A16;
            cpa16(sW + buf * WBUF + rr * P + j * 16, ws + (size_t)rr * CIN + j * 8);
        }
        asm volatile("cp.async.commit_group;" ::: "memory");
    };

    auto compute = [&](int pos, int buf) {
        const int ky = pos / 3, kx = pos - ky * 3;
        const uint32_t Wb = sW + buf * WBUF;
        const uint32_t arow = (uint32_t)((ky * 130 + kx + warpM * 32) * P);
        #pragma unroll
        for (int kh = 0; kh < NKH; kh++) {
            const uint32_t ko = kh * 32;
            uint32_t a[2][4];
            #pragma unroll
            for (int mi = 0; mi < 2; mi++)
                ldsm_x4(sA + arow + (uint32_t)(mi * 16 * P) + aoff + ko, a[mi]);
            #pragma unroll
            for (int np = 0; np < NPAIR; np++) {
                uint32_t w[4];
                ldsm_x4(Wb + (uint32_t)((warpN * WN + np * 16) * P) + boff + ko, w);
                #pragma unroll
                for (int mi = 0; mi < 2; mi++) {
                    mma_f16(acc[mi][2 * np],     a[mi], w[0], w[1]);
                    mma_f16(acc[mi][2 * np + 1], a[mi], w[2], w[3]);
                }
            }
            if (NT & 1) {
                uint32_t w[2];
                ldsm_x2(Wb + (uint32_t)((warpN * WN + (NT - 1) * 8) * P) + boff2 + ko, w);
                #pragma unroll
                for (int mi = 0; mi < 2; mi++)
                    mma_f16(acc[mi][NT - 1], a[mi], w[0], w[1]);
            }
        }
    };

    for (int kc = 0; kc < NKC; kc++) {
        __syncthreads();                     // prior readers of A buffer done
        stageA(kc);
        stageW(0, kc, 0);                    // A + W0 in one group
        asm volatile("cp.async.wait_group 0;" ::: "memory");
        __syncthreads();
        for (int pos = 0; pos < 9; pos++) {
            if (pos < 8) {
                stageW(pos + 1, kc, (pos + 1) & 1);
                // safe: buffer (pos+1)&1 last read by compute(pos-1),
                // which completed before the trailing __syncthreads.
            }
            compute(pos, pos & 1);
            if (pos < 8)
                asm volatile("cp.async.wait_group 0;" ::: "memory");
            __syncthreads();
        }
    }

    const int t2 = (lane & 3) * 2;

    if (EPI1) {
        // write fp16 padded plane for conv2
        #pragma unroll
        for (int mi = 0; mi < 2; mi++) {
            #pragma unroll
            for (int rr = 0; rr < 2; rr++) {
                const int px = x0 + warpM * 32 + mi * 16 + gr + rr * 8;
                const size_t flat = ((size_t)(n * Hp) + y + 1) * Wp + px + 1;
                __half* dh = g_A2 + flat * CIN2;
                #pragma unroll
                for (int ni = 0; ni < NT; ni++) {
                    const int co = warpN * WN + ni * 8 + t2;
                    float v0 = acc[mi][ni][rr * 2 + 0] + __ldg(bias + co);
                    float v1 = acc[mi][ni][rr * 2 + 1] + __ldg(bias + co + 1);
                    v0 = v0 > 0.f ? v0 : 0.1f * v0;
                    v1 = v1 > 0.f ? v1 : 0.1f * v1;
                    __half2 h = __floats2half2_rn(v0, v1);
                    *reinterpret_cast<uint32_t*>(dh + co) = *reinterpret_cast<uint32_t*>(&h);
                }
            }
        }
    } else {
        // ---- fused softmax + convex upsample + pixel shuffle ----
        float* sm = reinterpret_cast<float*>(smem);   // [128 px][145 pitch]
        __syncthreads();   // all compute done reading smem buffers
        #pragma unroll
        for (int mi = 0; mi < 2; mi++)
            #pragma unroll
            for (int rr = 0; rr < 2; rr++) {
                const int pxl = warpM * 32 + mi * 16 + gr + rr * 8;
                #pragma unroll
                for (int ni = 0; ni < NT; ni++) {
                    const int co = warpN * WN + ni * 8 + t2;
                    sm[pxl * 145 + co]     = acc[mi][ni][rr * 2 + 0] + __ldg(bias + co);
                    sm[pxl * 145 + co + 1] = acc[mi][ni][rr * 2 + 1] + __ldg(bias + co + 1);
                }
            }
        __syncthreads();

        const int pxl = tid >> 1, bh = tid & 1;
        const int x = x0 + pxl;

        float fpx[9], fpy[9];
        #pragma unroll
        for (int ki = 0; ki < 3; ki++)
            #pragma unroll
            for (int kj = 0; kj < 3; kj++) {
                const int k = ki * 3 + kj;
                const int yy = y + ki - 1, xx = x + kj - 1;
                const bool ok = (unsigned)yy < (unsigned)cH && (unsigned)xx < (unsigned)cW;
                fpx[k] = ok ? 4.0f * __ldg(flow + (size_t)(n * 2 + 0) * HW + yy * cW + xx) : 0.0f;
                fpy[k] = ok ? 4.0f * __ldg(flow + (size_t)(n * 2 + 1) * HW + yy * cW + xx) : 0.0f;
            }

        const int OH = 4 * cH, OW = 4 * cW;
        #pragma unroll
        for (int a = 0; a < 4; a++) {
            #pragma unroll
            for (int b2 = 0; b2 < 2; b2++) {
                const int b = bh * 2 + b2;
                float m[9], mx = -1e30f;
                #pragma unroll
                for (int k = 0; k < 9; k++) {
                    m[k] = 0.25f * sm[pxl * 145 + k * 16 + a * 4 + b];
                    mx = fmaxf(mx, m[k]);
                }
                float s = 0.0f;
                #pragma unroll
                for (int k = 0; k < 9; k++) { m[k] = __expf(m[k] - mx); s += m[k]; }
                const float inv = 1.0f / s;
                float ox = 0.0f, oy = 0.0f;
                #pragma unroll
                for (int k = 0; k < 9; k++) { ox += m[k] * fpx[k]; oy += m[k] * fpy[k]; }
                const int oyi = y * 4 + a, oxi = x * 4 + b;
                out[((size_t)(n * 2 + 0) * OH + oyi) * OW + oxi] = ox * inv;
                out[((size_t)(n * 2 + 1) * OH + oyi) * OW + oxi] = oy * inv;
            }
        }
    }
}

// ---------------------------------------------------------------------------
extern "C" void kernel_launch(void* const* d_in, const int* in_sizes, int n_in,
                              void* d_out, int out_size)
{
    (void)in_sizes; (void)n_in; (void)out_size;
    const float* flow = (const float*)d_in[0];
    const float* feat = (const float*)d_in[1];
    const float* w1   = (const float*)d_in[2];
    const float* b1   = (const float*)d_in[3];
    const float* w2   = (const float*)d_in[4];
    const float* b2   = (const float*)d_in[5];
    float* out = (float*)d_out;

    __half *a1, *a2, *w1s, *w2s;
    cudaGetSymbolAddress((void**)&a1,  g_A1);
    cudaGetSymbolAddress((void**)&a2,  g_A2);
    cudaGetSymbolAddress((void**)&w1s, g_W1);
    cudaGetSymbolAddress((void**)&w2s, g_W2);

    // conv1: KR=48, P=112: smem = 390*112 + 2*128*112 = 72,352  (2 CTAs/SM)
    constexpr int SM1 = 3 * 130 * (48 * 2 + 16) + 2 * COUT1 * (48 * 2 + 16);
    // conv2: KR=64, P=144: smem = 390*144 + 2*144*144 = 97,632  (2 CTAs/SM)
    constexpr int SM2 = 3 * 130 * (64 * 2 + 16) + 2 * COUT2 * (64 * 2 + 16);
    static_assert(SM2 >= 128 * 145 * 4, "epilogue smem");

    cudaFuncSetAttribute(conv_mma_kernel<CIN1, COUT1, 48, true>,
                         cudaFuncAttributeMaxDynamicSharedMemorySize, SM1);
    cudaFuncSetAttribute(conv_mma_kernel<CIN2, COUT2, 64, false>,
                         cudaFuncAttributeMaxDynamicSharedMemorySize, SM2);

    split_feat_kernel<<<(NPX + 127) / 128, 128>>>(feat);
    halo2_kernel<<<(NPX + 127) / 128, 128>>>();
    split_w_kernel<CIN1, COUT1><<<(9 * COUT1 * CIN1 + 255) / 256, 256>>>(w1, w1s);
    split_w_kernel<CIN2, COUT2><<<(9 * COUT2 * CIN2 + 255) / 256, 256>>>(w2, w2s);

    conv_mma_kernel<CIN1, COUT1, 48, true ><<<dim3(2, cH, cN), 256, SM1>>>(
        a1, w1s, b1, nullptr, nullptr);
    conv_mma_kernel<CIN2, COUT2, 64, false><<<dim3(2, cH, cN), 256, SM2>>>(
        a2, w2s, b2, flow, out);
}

// round 15
// speedup vs baseline: 2.9042x; 1.0320x over previous
#include <cuda_runtime.h>
#include <cuda_fp16.h>
#include <cstdint>
#include <math.h>

constexpr int cN = 4, cH = 128, cW = 256;
constexpr int CIN1 = 96,  COUT1 = 128;
constexpr int CIN2 = 128, COUT2 = 144;
constexpr int HW = cH * cW, Hp = cH + 2, Wp = cW + 2;
constexpr int NPX = cN * Hp * Wp;

// Static scratch (16B-aligned for cp.async / uint4)
__device__ __align__(256) __half g_A1[(size_t)NPX * CIN1];
__device__ __align__(256) __half g_A2[(size_t)NPX * CIN2];
__device__ __align__(256) __half g_W1[9 * COUT1 * CIN1];   // [pos][co][cin]
__device__ __align__(256) __half g_W2[9 * COUT2 * CIN2];

// ---------------- helpers ----------------------------------------------------
__device__ __forceinline__ uint32_t smem_u32(const void* p) {
    uint32_t a;
    asm("{ .reg .u64 t; cvta.to.shared.u64 t, %1; cvt.u32.u64 %0, t; }" : "=r"(a) : "l"(p));
    return a;
}
__device__ __forceinline__ void cpa16(uint32_t s, const void* g) {
    asm volatile("cp.async.cg.shared.global [%0], [%1], 16;" :: "r"(s), "l"(g) : "memory");
}
__device__ __forceinline__ void ldsm_x4(uint32_t a, uint32_t* r) {
    asm volatile("ldmatrix.sync.aligned.m8n8.x4.shared.b16 {%0,%1,%2,%3}, [%4];"
                 : "=r"(r[0]), "=r"(r[1]), "=r"(r[2]), "=r"(r[3]) : "r"(a));
}
__device__ __forceinline__ void ldsm_x2(uint32_t a, uint32_t* r) {
    asm volatile("ldmatrix.sync.aligned.m8n8.x2.shared.b16 {%0,%1}, [%2];"
                 : "=r"(r[0]), "=r"(r[1]) : "r"(a));
}
__device__ __forceinline__ void mma_f16(float* d, const uint32_t* a, uint32_t b0, uint32_t b1) {
    asm volatile("mma.sync.aligned.m16n8k16.row.col.f32.f16.f16.f32 "
        "{%0,%1,%2,%3}, {%4,%5,%6,%7}, {%8,%9}, {%0,%1,%2,%3};"
        : "+f"(d[0]), "+f"(d[1]), "+f"(d[2]), "+f"(d[3])
        : "r"(a[0]), "r"(a[1]), "r"(a[2]), "r"(a[3]), "r"(b0), "r"(b1));
}

// ---------------- prep: feat -> padded fp16 plane + A2 halo zero -------------
__global__ __launch_bounds__(128) void prep_feat_kernel(const float* __restrict__ feat)
{
    int flat = blockIdx.x * 128 + threadIdx.x;
    if (flat >= NPX) return;
    int xp = flat % Wp, yp = (flat / Wp) % Hp, n = flat / (Hp * Wp);
    bool interior = (yp >= 1 && yp <= cH && xp >= 1 && xp <= cW);
    __half* dh = g_A1 + (size_t)flat * CIN1;

    if (!interior) {   // fused halo-zero for conv2's input plane
        uint4 z = {0, 0, 0, 0};
        uint4* d2 = reinterpret_cast<uint4*>(g_A2 + (size_t)flat * CIN2);
        #pragma unroll
        for (int j = 0; j < 16; j++) d2[j] = z;
    }
    #pragma unroll
    for (int c = 0; c < 3; c++) {
        uint32_t hw[16];
        if (interior) {
            const float* src = feat + ((size_t)(n * CIN1 + c * 32) * cH + (yp - 1)) * cW + (xp - 1);
            #pragma unroll
            for (int i = 0; i < 16; i++) {
                __half2 h = __floats2half2_rn(src[(size_t)(2 * i) * HW],
                                              src[(size_t)(2 * i + 1) * HW]);
                hw[i] = *reinterpret_cast<uint32_t*>(&h);
            }
        } else {
            #pragma unroll
            for (int i = 0; i < 16; i++) hw[i] = 0;
        }
        #pragma unroll
        for (int j = 0; j < 4; j++)
            *reinterpret_cast<uint4*>(dh + c * 32 + j * 8) = *reinterpret_cast<uint4*>(hw + j * 4);
    }
}

// both weight tensors OIHW fp32 -> [pos][co][cin] fp16 in one launch
__global__ __launch_bounds__(256) void prep_w_kernel(const float* __restrict__ w1,
                                                     const float* __restrict__ w2)
{
    constexpr int N1 = 9 * COUT1 * CIN1;
    constexpr int N2 = 9 * COUT2 * CIN2;
    int idx = blockIdx.x * 256 + threadIdx.x;
    if (idx < N1) {
        int ci = idx % CIN1; int t = idx / CIN1;
        int co = t % COUT1, pos = t / COUT1;
        g_W1[idx] = __float2half(w1[((size_t)co * CIN1 + ci) * 9 + pos]);
    } else if (idx < N1 + N2) {
        int k = idx - N1;
        int ci = k % CIN2; int t = k / CIN2;
        int co = t % COUT2, pos = t / COUT2;
        g_W2[k] = __float2half(w2[((size_t)co * CIN2 + ci) * 9 + pos]);
    }
}

// ---------------- HMMA fp16 conv: CTA = 128px x NCO, 8 warps (4M x 2N) -------
// A-chunk-stationary staging; W double-buffered per position.
// EPI1: smem-bounced coalesced fp16 plane write. Else: fused softmax+upsample.
template<int CIN, int NCO, int KR, bool EPI1>
__global__ __launch_bounds__(256, 2) void conv_mma_kernel(
    const __half* __restrict__ Ap, const __half* __restrict__ Wv,
    const float* __restrict__ bias,
    const float* __restrict__ flow, float* __restrict__ out)
{
    constexpr int NKC = CIN / KR;               // k-chunks
    constexpr int NKH = KR / 16;                // kh steps per position
    constexpr int A16 = KR / 8;                 // 16B segments per row
    constexpr int P   = KR * 2 + 16;            // smem row pitch (bytes)
    constexpr int AROWS = 3 * 130;              // staged A rows per chunk
    constexpr int WN  = NCO / 2;                // co per warp-N group
    constexpr int NT  = NCO / 16;               // n-tiles per warp (8 / 9)
    constexpr int NPAIR = NT / 2;
    constexpr int ABUF = AROWS * P;
    constexpr int WBUF = NCO * P;

    extern __shared__ __align__(16) char smem[];
    const uint32_t sA = smem_u32(smem);
    const uint32_t sW = sA + ABUF;

    const int tid = threadIdx.x, lane = tid & 31, wid = tid >> 5;
    const int warpM = wid & 3, warpN = wid >> 2;
    const int gr = lane >> 2;

    const uint32_t aoff = (uint32_t)((lane & 15) * P + (lane >> 4) * 16);
    const uint32_t boff = (uint32_t)((((lane >> 4) << 3) + (lane & 7)) * P + ((lane >> 3) & 1) * 16);
    const uint32_t boff2 = (uint32_t)((lane & 7) * P + ((lane >> 3) & 1) * 16);

    const int x0 = blockIdx.x * 128, y = blockIdx.y, n = blockIdx.z;

    float acc[2][NT][4];
    #pragma unroll
    for (int mi = 0; mi < 2; mi++)
        #pragma unroll
        for (int ni = 0; ni < NT; ni++)
            #pragma unroll
            for (int j = 0; j < 4; j++) acc[mi][ni][j] = 0.0f;

    auto stageA = [&](int kc) {
        const size_t rowb = (size_t)(n * Hp + y) * Wp + x0;
        for (int idx = tid; idx < AROWS * A16; idx += 256) {
            int rr = idx / A16, j = idx % A16;
            int ky = rr / 130, px = rr - ky * 130;
            cpa16(sA + rr * P + j * 16,
                  Ap + (rowb + (size_t)ky * Wp + px) * CIN + kc * KR + j * 8);
        }
    };
    auto stageW = [&](int pos, int kc, int buf) {
        const __half* ws = Wv + (size_t)pos * NCO * CIN + kc * KR;
        for (int idx = tid; idx < NCO * A16; idx += 256) {
            int rr = idx / A16, j = idx % A16;
            cpa16(sW + buf * WBUF + rr * P + j * 16, ws + (size_t)rr * CIN + j * 8);
        }
        asm volatile("cp.async.commit_group;" ::: "memory");
    };

    auto compute = [&](int pos, int buf) {
        const int ky = pos / 3, kx = pos - ky * 3;
        const uint32_t Wb = sW + buf * WBUF;
        const uint32_t arow = (uint32_t)((ky * 130 + kx + warpM * 32) * P);
        #pragma unroll
        for (int kh = 0; kh < NKH; kh++) {
            const uint32_t ko = kh * 32;
            uint32_t a[2][4];
            #pragma unroll
            for (int mi = 0; mi < 2; mi++)
                ldsm_x4(sA + arow + (uint32_t)(mi * 16 * P) + aoff + ko, a[mi]);
            #pragma unroll
            for (int np = 0; np < NPAIR; np++) {
                uint32_t w[4];
                ldsm_x4(Wb + (uint32_t)((warpN * WN + np * 16) * P) + boff + ko, w);
                #pragma unroll
                for (int mi = 0; mi < 2; mi++) {
                    mma_f16(acc[mi][2 * np],     a[mi], w[0], w[1]);
                    mma_f16(acc[mi][2 * np + 1], a[mi], w[2], w[3]);
                }
            }
            if (NT & 1) {
                uint32_t w[2];
                ldsm_x2(Wb + (uint32_t)((warpN * WN + (NT - 1) * 8) * P) + boff2 + ko, w);
                #pragma unroll
                for (int mi = 0; mi < 2; mi++)
                    mma_f16(acc[mi][NT - 1], a[mi], w[0], w[1]);
            }
        }
    };

    for (int kc = 0; kc < NKC; kc++) {
        __syncthreads();                     // prior readers of A buffer done
        stageA(kc);
        stageW(0, kc, 0);                    // A + W0 in one group
        asm volatile("cp.async.wait_group 0;" ::: "memory");
        __syncthreads();
        for (int pos = 0; pos < 9; pos++) {
            if (pos < 8) stageW(pos + 1, kc, (pos + 1) & 1);
            compute(pos, pos & 1);
            if (pos < 8)
                asm volatile("cp.async.wait_group 0;" ::: "memory");
            __syncthreads();
        }
    }

    const int t2 = (lane & 3) * 2;

    if (EPI1) {
        // ---- smem-bounced coalesced plane write ----
        // pitch 136 halves: STS bank-walk = 68*gr mod 32 in {0,4,..,28} + (0..3)
        __half* sm16 = reinterpret_cast<__half*>(smem);
        __syncthreads();   // compute done reading A/W buffers
        #pragma unroll
        for (int mi = 0; mi < 2; mi++)
            #pragma unroll
            for (int rr = 0; rr < 2; rr++) {
                const int pxl = warpM * 32 + mi * 16 + gr + rr * 8;
                #pragma unroll
                for (int ni = 0; ni < NT; ni++) {
                    const int co = warpN * WN + ni * 8 + t2;
                    float v0 = acc[mi][ni][rr * 2 + 0] + __ldg(bias + co);
                    float v1 = acc[mi][ni][rr * 2 + 1] + __ldg(bias + co + 1);
                    v0 = v0 > 0.f ? v0 : 0.1f * v0;
                    v1 = v1 > 0.f ? v1 : 0.1f * v1;
                    __half2 h = __floats2half2_rn(v0, v1);
                    *reinterpret_cast<uint32_t*>(sm16 + pxl * 136 + co) =
                        *reinterpret_cast<uint32_t*>(&h);
                }
            }
        __syncthreads();
        // coalesced store: thread = (px, half); 8x16B contiguous per thread
        const int px = tid >> 1, hf = tid & 1;
        const size_t flat = ((size_t)(n * Hp) + y + 1) * Wp + (x0 + px) + 1;
        uint4* dst = reinterpret_cast<uint4*>(g_A2 + flat * CIN2 + hf * 64);
        const uint4* srcp = reinterpret_cast<const uint4*>(sm16 + px * 136 + hf * 64);
        #pragma unroll
        for (int j = 0; j < 8; j++) dst[j] = srcp[j];
    } else {
        // ---- fused softmax + convex upsample + pixel shuffle ----
        float* sm = reinterpret_cast<float*>(smem);   // [128 px][145 pitch]
        __syncthreads();   // compute done reading smem buffers
        #pragma unroll
        for (int mi = 0; mi < 2; mi++)
            #pragma unroll
            for (int rr = 0; rr < 2; rr++) {
                const int pxl = warpM * 32 + mi * 16 + gr + rr * 8;
                #pragma unroll
                for (int ni = 0; ni < NT; ni++) {
                    const int co = warpN * WN + ni * 8 + t2;
                    sm[pxl * 145 + co]     = acc[mi][ni][rr * 2 + 0] + __ldg(bias + co);
                    sm[pxl * 145 + co + 1] = acc[mi][ni][rr * 2 + 1] + __ldg(bias + co + 1);
                }
            }
        __syncthreads();

        const int pxl = tid >> 1, bh = tid & 1;
        const int x = x0 + pxl;

        float fpx[9], fpy[9];
        #pragma unroll
        for (int ki = 0; ki < 3; ki++)
            #pragma unroll
            for (int kj = 0; kj < 3; kj++) {
                const int k = ki * 3 + kj;
                const int yy = y + ki - 1, xx = x + kj - 1;
                const bool ok = (unsigned)yy < (unsigned)cH && (unsigned)xx < (unsigned)cW;
                fpx[k] = ok ? 4.0f * __ldg(flow + (size_t)(n * 2 + 0) * HW + yy * cW + xx) : 0.0f;
                fpy[k] = ok ? 4.0f * __ldg(flow + (size_t)(n * 2 + 1) * HW + yy * cW + xx) : 0.0f;
            }

        const int OH = 4 * cH, OW = 4 * cW;
        #pragma unroll
        for (int a = 0; a < 4; a++) {
            #pragma unroll
            for (int b2 = 0; b2 < 2; b2++) {
                const int b = bh * 2 + b2;
                float m[9], mx = -1e30f;
                #pragma unroll
                for (int k = 0; k < 9; k++) {
                    m[k] = 0.25f * sm[pxl * 145 + k * 16 + a * 4 + b];
                    mx = fmaxf(mx, m[k]);
                }
                float s = 0.0f;
                #pragma unroll
                for (int k = 0; k < 9; k++) { m[k] = __expf(m[k] - mx); s += m[k]; }
                const float inv = 1.0f / s;
                float ox = 0.0f, oy = 0.0f;
                #pragma unroll
                for (int k = 0; k < 9; k++) { ox += m[k] * fpx[k]; oy += m[k] * fpy[k]; }
                const int oyi = y * 4 + a, oxi = x * 4 + b;
                out[((size_t)(n * 2 + 0) * OH + oyi) * OW + oxi] = ox * inv;
                out[((size_t)(n * 2 + 1) * OH + oyi) * OW + oxi] = oy * inv;
            }
        }
    }
}

// ---------------------------------------------------------------------------
extern "C" void kernel_launch(void* const* d_in, const int* in_sizes, int n_in,
                              void* d_out, int out_size)
{
    (void)in_sizes; (void)n_in; (void)out_size;
    const float* flow = (const float*)d_in[0];
    const float* feat = (const float*)d_in[1];
    const float* w1   = (const float*)d_in[2];
    const float* b1   = (const float*)d_in[3];
    const float* w2   = (const float*)d_in[4];
    const float* b2   = (const float*)d_in[5];
    float* out = (float*)d_out;

    __half *a1, *a2, *w1s, *w2s;
    cudaGetSymbolAddress((void**)&a1,  g_A1);
    cudaGetSymbolAddress((void**)&a2,  g_A2);
    cudaGetSymbolAddress((void**)&w1s, g_W1);
    cudaGetSymbolAddress((void**)&w2s, g_W2);

    // conv1: KR=48, P=112: smem = 390*112 + 2*128*112 = 72,352
    //   (>= epilogue bounce 128*136*2 = 34,816)
    constexpr int SM1 = 3 * 130 * (48 * 2 + 16) + 2 * COUT1 * (48 * 2 + 16);
    static_assert(SM1 >= 128 * 136 * 2, "epi1 smem");
    // conv2: KR=64, P=144: smem = 390*144 + 2*144*144 = 97,632
    constexpr int SM2 = 3 * 130 * (64 * 2 + 16) + 2 * COUT2 * (64 * 2 + 16);
    static_assert(SM2 >= 128 * 145 * 4, "epilogue smem");

    cudaFuncSetAttribute(conv_mma_kernel<CIN1, COUT1, 48, true>,
                         cudaFuncAttributeMaxDynamicSharedMemorySize, SM1);
    cudaFuncSetAttribute(conv_mma_kernel<CIN2, COUT2, 64, false>,
                         cudaFuncAttributeMaxDynamicSharedMemorySize, SM2);

    prep_feat_kernel<<<(NPX + 127) / 128, 128>>>(feat);
    constexpr int NW = 9 * COUT1 * CIN1 + 9 * COUT2 * CIN2;
    prep_w_kernel<<<(NW + 255) / 256, 256>>>(w1, w2);

    conv_mma_kernel<CIN1, COUT1, 48, true ><<<dim3(2, cH, cN), 256, SM1>>>(
        a1, w1s, b1, nullptr, nullptr);
    conv_mma_kernel<CIN2, COUT2, 64, false><<<dim3(2, cH, cN), 256, SM2>>>(
        a2, w2s, b2, flow, out);
}

// round 16
// speedup vs baseline: 2.9354x; 1.0107x over previous
#include <cuda_runtime.h>
#include <cuda_fp16.h>
#include <cstdint>
#include <math.h>

constexpr int cN = 4, cH = 128, cW = 256;
constexpr int CIN1 = 96,  COUT1 = 128;
constexpr int CIN2 = 128, COUT2 = 144;
constexpr int HW = cH * cW, Hp = cH + 2, Wp = cW + 2;
constexpr int NPX = cN * Hp * Wp;

// Static scratch (16B-aligned for cp.async / uint4)
__device__ __align__(256) __half g_A1[(size_t)NPX * CIN1];
__device__ __align__(256) __half g_A2[(size_t)NPX * CIN2];
__device__ __align__(256) __half g_W1[9 * COUT1 * CIN1];   // [pos][co][cin]
__device__ __align__(256) __half g_W2[9 * COUT2 * CIN2];

// ---------------- helpers ----------------------------------------------------
__device__ __forceinline__ uint32_t smem_u32(const void* p) {
    uint32_t a;
    asm("{ .reg .u64 t; cvta.to.shared.u64 t, %1; cvt.u32.u64 %0, t; }" : "=r"(a) : "l"(p));
    return a;
}
__device__ __forceinline__ void cpa16(uint32_t s, const void* g) {
    asm volatile("cp.async.cg.shared.global [%0], [%1], 16;" :: "r"(s), "l"(g) : "memory");
}
__device__ __forceinline__ void ldsm_x4(uint32_t a, uint32_t* r) {
    asm volatile("ldmatrix.sync.aligned.m8n8.x4.shared.b16 {%0,%1,%2,%3}, [%4];"
                 : "=r"(r[0]), "=r"(r[1]), "=r"(r[2]), "=r"(r[3]) : "r"(a));
}
__device__ __forceinline__ void ldsm_x2(uint32_t a, uint32_t* r) {
    asm volatile("ldmatrix.sync.aligned.m8n8.x2.shared.b16 {%0,%1}, [%2];"
                 : "=r"(r[0]), "=r"(r[1]) : "r"(a));
}
__device__ __forceinline__ void mma_f16(float* d, const uint32_t* a, uint32_t b0, uint32_t b1) {
    asm volatile("mma.sync.aligned.m16n8k16.row.col.f32.f16.f16.f32 "
        "{%0,%1,%2,%3}, {%4,%5,%6,%7}, {%8,%9}, {%0,%1,%2,%3};"
        : "+f"(d[0]), "+f"(d[1]), "+f"(d[2]), "+f"(d[3])
        : "r"(a[0]), "r"(a[1]), "r"(a[2]), "r"(a[3]), "r"(b0), "r"(b1));
}

// ---------------- prep: feat -> padded fp16 plane + A2 halo zero -------------
__global__ __launch_bounds__(128) void prep_feat_kernel(const float* __restrict__ feat)
{
    int flat = blockIdx.x * 128 + threadIdx.x;
    if (flat >= NPX) return;
    int xp = flat % Wp, yp = (flat / Wp) % Hp, n = flat / (Hp * Wp);
    bool interior = (yp >= 1 && yp <= cH && xp >= 1 && xp <= cW);
    __half* dh = g_A1 + (size_t)flat * CIN1;

    if (!interior) {   // fused halo-zero for conv2's input plane
        uint4 z = {0, 0, 0, 0};
        uint4* d2 = reinterpret_cast<uint4*>(g_A2 + (size_t)flat * CIN2);
        #pragma unroll
        for (int j = 0; j < 16; j++) d2[j] = z;
    }
    #pragma unroll
    for (int c = 0; c < 3; c++) {
        uint32_t hw[16];
        if (interior) {
            const float* src = feat + ((size_t)(n * CIN1 + c * 32) * cH + (yp - 1)) * cW + (xp - 1);
            #pragma unroll
            for (int i = 0; i < 16; i++) {
                __half2 h = __floats2half2_rn(src[(size_t)(2 * i) * HW],
                                              src[(size_t)(2 * i + 1) * HW]);
                hw[i] = *reinterpret_cast<uint32_t*>(&h);
            }
        } else {
            #pragma unroll
            for (int i = 0; i < 16; i++) hw[i] = 0;
        }
        #pragma unroll
        for (int j = 0; j < 4; j++)
            *reinterpret_cast<uint4*>(dh + c * 32 + j * 8) = *reinterpret_cast<uint4*>(hw + j * 4);
    }
}

// both weight tensors OIHW fp32 -> [pos][co][cin] fp16 in one launch
__global__ __launch_bounds__(256) void prep_w_kernel(const float* __restrict__ w1,
                                                     const float* __restrict__ w2)
{
    constexpr int N1 = 9 * COUT1 * CIN1;
    constexpr int N2 = 9 * COUT2 * CIN2;
    int idx = blockIdx.x * 256 + threadIdx.x;
    if (idx < N1) {
        int ci = idx % CIN1; int t = idx / CIN1;
        int co = t % COUT1, pos = t / COUT1;
        g_W1[idx] = __float2half(w1[((size_t)co * CIN1 + ci) * 9 + pos]);
    } else if (idx < N1 + N2) {
        int k = idx - N1;
        int ci = k % CIN2; int t = k / CIN2;
        int co = t % COUT2, pos = t / COUT2;
        g_W2[k] = __float2half(w2[((size_t)co * CIN2 + ci) * 9 + pos]);
    }
}

// ---------------- HMMA fp16 conv: CTA = 128px x NCO, 8 warps (4M x 2N) -------
// KR=32 k-chunks; A halo window (3 x 130 rows) staged once per chunk.
// W staged per ky-ROW (3 positions at once), double-buffered -> one barrier
// interval covers 3 positions (3x the MMAs between syncs).
// EPI1: smem-bounced coalesced fp16 plane write. Else: fused softmax+upsample.
template<int CIN, int NCO, bool EPI1>
__global__ __launch_bounds__(256, 2) void conv_mma_kernel(
    const __half* __restrict__ Ap, const __half* __restrict__ Wv,
    const float* __restrict__ bias,
    const float* __restrict__ flow, float* __restrict__ out)
{
    constexpr int KR  = 32;
    constexpr int NKC = CIN / KR;               // k-chunks (3 / 4)
    constexpr int NKH = KR / 16;                // 2 kh steps
    constexpr int A16 = KR / 8;                 // 4 x 16B segments per row
    constexpr int P   = 80;                     // pitch: 20r mod 32 conflict-free
    constexpr int AROWS = 3 * 130;
    constexpr int WN  = NCO / 2;
    constexpr int NT  = NCO / 16;               // 8 / 9
    constexpr int NPAIR = NT / 2;
    constexpr int ABUF  = AROWS * P;            // 31,200
    constexpr int WBUF3 = 3 * NCO * P;          // one ky-row of W (3 positions)

    extern __shared__ __align__(16) char smem[];
    const uint32_t sA = smem_u32(smem);
    const uint32_t sW = sA + ABUF;

    const int tid = threadIdx.x, lane = tid & 31, wid = tid >> 5;
    const int warpM = wid & 3, warpN = wid >> 2;
    const int gr = lane >> 2;

    const uint32_t aoff = (uint32_t)((lane & 15) * P + (lane >> 4) * 16);
    const uint32_t boff = (uint32_t)((((lane >> 4) << 3) + (lane & 7)) * P + ((lane >> 3) & 1) * 16);
    const uint32_t boff2 = (uint32_t)((lane & 7) * P + ((lane >> 3) & 1) * 16);

    const int x0 = blockIdx.x * 128, y = blockIdx.y, n = blockIdx.z;

    float acc[2][NT][4];
    #pragma unroll
    for (int mi = 0; mi < 2; mi++)
        #pragma unroll
        for (int ni = 0; ni < NT; ni++)
            #pragma unroll
            for (int j = 0; j < 4; j++) acc[mi][ni][j] = 0.0f;

    auto stageA = [&](int kc) {
        const size_t rowb = (size_t)(n * Hp + y) * Wp + x0;
        for (int idx = tid; idx < AROWS * A16; idx += 256) {
            int rr = idx / A16, j = idx % A16;
            int ky = rr / 130, px = rr - ky * 130;
            cpa16(sA + rr * P + j * 16,
                  Ap + (rowb + (size_t)ky * Wp + px) * CIN + kc * KR + j * 8);
        }
    };
    // stage one ky-row: positions ky*3 .. ky*3+2, layout [kx][co][P]
    auto stageW3 = [&](int ky, int kc, int buf) {
        const __half* ws = Wv + ((size_t)ky * 3) * NCO * CIN + kc * KR;
        for (int idx = tid; idx < 3 * NCO * A16; idx += 256) {
            int rr = idx / A16, j = idx % A16;   // rr = kx*NCO + co
            cpa16(sW + buf * WBUF3 + rr * P + j * 16,
                  ws + (size_t)rr * CIN + j * 8);
        }
        asm volatile("cp.async.commit_group;" ::: "memory");
    };

    auto compute3 = [&](int ky, int buf) {
        const uint32_t Wb0 = sW + buf * WBUF3;
        #pragma unroll
        for (int kx = 0; kx < 3; kx++) {
            const uint32_t Wb = Wb0 + (uint32_t)(kx * NCO * P);
            const uint32_t arow = (uint32_t)((ky * 130 + kx + warpM * 32) * P);
            #pragma unroll
            for (int kh = 0; kh < NKH; kh++) {
                const uint32_t ko = kh * 32;
                uint32_t a[2][4];
                #pragma unroll
                for (int mi = 0; mi < 2; mi++)
                    ldsm_x4(sA + arow + (uint32_t)(mi * 16 * P) + aoff + ko, a[mi]);
                #pragma unroll
                for (int np = 0; np < NPAIR; np++) {
                    uint32_t w[4];
                    ldsm_x4(Wb + (uint32_t)((warpN * WN + np * 16) * P) + boff + ko, w);
                    #pragma unroll
                    for (int mi = 0; mi < 2; mi++) {
                        mma_f16(acc[mi][2 * np],     a[mi], w[0], w[1]);
                        mma_f16(acc[mi][2 * np + 1], a[mi], w[2], w[3]);
                    }
                }
                if (NT & 1) {
                    uint32_t w[2];
                    ldsm_x2(Wb + (uint32_t)((warpN * WN + (NT - 1) * 8) * P) + boff2 + ko, w);
                    #pragma unroll
                    for (int mi = 0; mi < 2; mi++)
                        mma_f16(acc[mi][NT - 1], a[mi], w[0], w[1]);
                }
            }
        }
    };

    for (int kc = 0; kc < NKC; kc++) {
        __syncthreads();                     // prior readers of A/W buffers done
        stageA(kc);
        stageW3(0, kc, 0);                   // A + W row 0 in one group
        asm volatile("cp.async.wait_group 0;" ::: "memory");
        __syncthreads();
        #pragma unroll
        for (int ky = 0; ky < 3; ky++) {
            if (ky < 2) stageW3(ky + 1, kc, (ky + 1) & 1);
            compute3(ky, ky & 1);
            if (ky < 2)
                asm volatile("cp.async.wait_group 0;" ::: "memory");
            __syncthreads();
        }
    }

    const int t2 = (lane & 3) * 2;

    if (EPI1) {
        // ---- smem-bounced coalesced plane write (pitch 136 halves) ----
        __half* sm16 = reinterpret_cast<__half*>(smem);
        __syncthreads();
        #pragma unroll
        for (int mi = 0; mi < 2; mi++)
            #pragma unroll
            for (int rr = 0; rr < 2; rr++) {
                const int pxl = warpM * 32 + mi * 16 + gr + rr * 8;
                #pragma unroll
                for (int ni = 0; ni < NT; ni++) {
                    const int co = warpN * WN + ni * 8 + t2;
                    float v0 = acc[mi][ni][rr * 2 + 0] + __ldg(bias + co);
                    float v1 = acc[mi][ni][rr * 2 + 1] + __ldg(bias + co + 1);
                    v0 = v0 > 0.f ? v0 : 0.1f * v0;
                    v1 = v1 > 0.f ? v1 : 0.1f * v1;
                    __half2 h = __floats2half2_rn(v0, v1);
                    *reinterpret_cast<uint32_t*>(sm16 + pxl * 136 + co) =
                        *reinterpret_cast<uint32_t*>(&h);
                }
            }
        __syncthreads();
        const int px = tid >> 1, hf = tid & 1;
        const size_t flat = ((size_t)(n * Hp) + y + 1) * Wp + (x0 + px) + 1;
        uint4* dst = reinterpret_cast<uint4*>(g_A2 + flat * CIN2 + hf * 64);
        const uint4* srcp = reinterpret_cast<const uint4*>(sm16 + px * 136 + hf * 64);
        #pragma unroll
        for (int j = 0; j < 8; j++) dst[j] = srcp[j];
    } else {
        // ---- fused softmax + convex upsample + pixel shuffle ----
        float* sm = reinterpret_cast<float*>(smem);   // [128 px][145 pitch]
        __syncthreads();
        #pragma unroll
        for (int mi = 0; mi < 2; mi++)
            #pragma unroll
            for (int rr = 0; rr < 2; rr++) {
                const int pxl = warpM * 32 + mi * 16 + gr + rr * 8;
                #pragma unroll
                for (int ni = 0; ni < NT; ni++) {
                    const int co = warpN * WN + ni * 8 + t2;
                    sm[pxl * 145 + co]     = acc[mi][ni][rr * 2 + 0] + __ldg(bias + co);
                    sm[pxl * 145 + co + 1] = acc[mi][ni][rr * 2 + 1] + __ldg(bias + co + 1);
                }
            }
        __syncthreads();

        const int pxl = tid >> 1, bh = tid & 1;
        const int x = x0 + pxl;

        float fpx[9], fpy[9];
        #pragma unroll
        for (int ki = 0; ki < 3; ki++)
            #pragma unroll
            for (int kj = 0; kj < 3; kj++) {
                const int k = ki * 3 + kj;
                const int yy = y + ki - 1, xx = x + kj - 1;
                const bool ok = (unsigned)yy < (unsigned)cH && (unsigned)xx < (unsigned)cW;
                fpx[k] = ok ? 4.0f * __ldg(flow + (size_t)(n * 2 + 0) * HW + yy * cW + xx) : 0.0f;
                fpy[k] = ok ? 4.0f * __ldg(flow + (size_t)(n * 2 + 1) * HW + yy * cW + xx) : 0.0f;
            }

        const int OH = 4 * cH, OW = 4 * cW;
        #pragma unroll
        for (int a = 0; a < 4; a++) {
            #pragma unroll
            for (int b2 = 0; b2 < 2; b2++) {
                const int b = bh * 2 + b2;
                float m[9], mx = -1e30f;
                #pragma unroll
                for (int k = 0; k < 9; k++) {
                    m[k] = 0.25f * sm[pxl * 145 + k * 16 + a * 4 + b];
                    mx = fmaxf(mx, m[k]);
                }
                float s = 0.0f;
                #pragma unroll
                for (int k = 0; k < 9; k++) { m[k] = __expf(m[k] - mx); s += m[k]; }
                const float inv = 1.0f / s;
                float ox = 0.0f, oy = 0.0f;
                #pragma unroll
                for (int k = 0; k < 9; k++) { ox += m[k] * fpx[k]; oy += m[k] * fpy[k]; }
                const int oyi = y * 4 + a, oxi = x * 4 + b;
                out[((size_t)(n * 2 + 0) * OH + oyi) * OW + oxi] = ox * inv;
                out[((size_t)(n * 2 + 1) * OH + oyi) * OW + oxi] = oy * inv;
            }
        }
    }
}

// ---------------------------------------------------------------------------
extern "C" void kernel_launch(void* const* d_in, const int* in_sizes, int n_in,
                              void* d_out, int out_size)
{
    (void)in_sizes; (void)n_in; (void)out_size;
    const float* flow = (const float*)d_in[0];
    const float* feat = (const float*)d_in[1];
    const float* w1   = (const float*)d_in[2];
    const float* b1   = (const float*)d_in[3];
    const float* w2   = (const float*)d_in[4];
    const float* b2   = (const float*)d_in[5];
    float* out = (float*)d_out;

    __half *a1, *a2, *w1s, *w2s;
    cudaGetSymbolAddress((void**)&a1,  g_A1);
    cudaGetSymbolAddress((void**)&a2,  g_A2);
    cudaGetSymbolAddress((void**)&w1s, g_W1);
    cudaGetSymbolAddress((void**)&w2s, g_W2);

    // conv1: A 390*80 + 2*3*128*80 = 92,640  (>= epi bounce 34,816)
    constexpr int SM1 = 3 * 130 * 80 + 2 * 3 * COUT1 * 80;
    static_assert(SM1 >= 128 * 136 * 2, "epi1 smem");
    // conv2: A 390*80 + 2*3*144*80 = 100,320 (>= epi 74,240); 2 CTAs = 200,640
    constexpr int SM2 = 3 * 130 * 80 + 2 * 3 * COUT2 * 80;
    static_assert(SM2 >= 128 * 145 * 4, "epilogue smem");

    cudaFuncSetAttribute(conv_mma_kernel<CIN1, COUT1, true>,
                         cudaFuncAttributeMaxDynamicSharedMemorySize, SM1);
    cudaFuncSetAttribute(conv_mma_kernel<CIN2, COUT2, false>,
                         cudaFuncAttributeMaxDynamicSharedMemorySize, SM2);

    prep_feat_kernel<<<(NPX + 127) / 128, 128>>>(feat);
    constexpr int NW = 9 * COUT1 * CIN1 + 9 * COUT2 * CIN2;
    prep_w_kernel<<<(NW + 255) / 256, 256>>>(w1, w2);

    conv_mma_kernel<CIN1, COUT1, true ><<<dim3(2, cH, cN), 256, SM1>>>(
        a1, w1s, b1, nullptr, nullptr);
    conv_mma_kernel<CIN2, COUT2, false><<<dim3(2, cH, cN), 256, SM2>>>(
        a2, w2s, b2, flow, out);
}

// round 17
// speedup vs baseline: 3.0063x; 1.0241x over previous
#include <cuda_runtime.h>
#include <cuda_fp16.h>
#include <cstdint>
#include <math.h>

constexpr int cN = 4, cH = 128, cW = 256;
constexpr int CIN1 = 96,  COUT1 = 128;
constexpr int CIN2 = 128, COUT2 = 144;
constexpr int HW = cH * cW, Hp = cH + 2, Wp = cW + 2;
constexpr int NPX = cN * Hp * Wp;

// Static scratch (16B-aligned for cp.async / uint4)
__device__ __align__(256) __half g_A1[(size_t)NPX * CIN1];
__device__ __align__(256) __half g_A2[(size_t)NPX * CIN2];
__device__ __align__(256) __half g_W1[9 * COUT1 * CIN1];   // [pos][co][cin]
__device__ __align__(256) __half g_W2[9 * COUT2 * CIN2];

// ---------------- helpers ----------------------------------------------------
__device__ __forceinline__ uint32_t smem_u32(const void* p) {
    uint32_t a;
    asm("{ .reg .u64 t; cvta.to.shared.u64 t, %1; cvt.u32.u64 %0, t; }" : "=r"(a) : "l"(p));
    return a;
}
__device__ __forceinline__ void cpa16(uint32_t s, const void* g) {
    asm volatile("cp.async.cg.shared.global [%0], [%1], 16;" :: "r"(s), "l"(g) : "memory");
}
__device__ __forceinline__ void ldsm_x4(uint32_t a, uint32_t* r) {
    asm volatile("ldmatrix.sync.aligned.m8n8.x4.shared.b16 {%0,%1,%2,%3}, [%4];"
                 : "=r"(r[0]), "=r"(r[1]), "=r"(r[2]), "=r"(r[3]) : "r"(a));
}
__device__ __forceinline__ void ldsm_x2(uint32_t a, uint32_t* r) {
    asm volatile("ldmatrix.sync.aligned.m8n8.x2.shared.b16 {%0,%1}, [%2];"
                 : "=r"(r[0]), "=r"(r[1]) : "r"(a));
}
__device__ __forceinline__ void mma_f16(float* d, const uint32_t* a, uint32_t b0, uint32_t b1) {
    asm volatile("mma.sync.aligned.m16n8k16.row.col.f32.f16.f16.f32 "
        "{%0,%1,%2,%3}, {%4,%5,%6,%7}, {%8,%9}, {%0,%1,%2,%3};"
        : "+f"(d[0]), "+f"(d[1]), "+f"(d[2]), "+f"(d[3])
        : "r"(a[0]), "r"(a[1]), "r"(a[2]), "r"(a[3]), "r"(b0), "r"(b1));
}

// ---------------- fused prep: feat plane + halo zero + both W transposes -----
constexpr int FEAT_BLOCKS = (NPX + 127) / 128;                     // 1049
constexpr int NW_TOTAL = 9 * COUT1 * CIN1 + 9 * COUT2 * CIN2;      // 276,480
constexpr int W_BLOCKS = (NW_TOTAL + 127) / 128;

__global__ __launch_bounds__(128) void prep_kernel(const float* __restrict__ feat,
                                                   const float* __restrict__ w1,
                                                   const float* __restrict__ w2)
{
    if (blockIdx.x < FEAT_BLOCKS) {
        int flat = blockIdx.x * 128 + threadIdx.x;
        if (flat >= NPX) return;
        int xp = flat % Wp, yp = (flat / Wp) % Hp, n = flat / (Hp * Wp);
        bool interior = (yp >= 1 && yp <= cH && xp >= 1 && xp <= cW);
        __half* dh = g_A1 + (size_t)flat * CIN1;

        if (!interior) {   // fused halo-zero for conv2's input plane
            uint4 z = {0, 0, 0, 0};
            uint4* d2 = reinterpret_cast<uint4*>(g_A2 + (size_t)flat * CIN2);
            #pragma unroll
            for (int j = 0; j < 16; j++) d2[j] = z;
        }
        #pragma unroll
        for (int c = 0; c < 3; c++) {
            uint32_t hw[16];
            if (interior) {
                const float* src = feat +
                    ((size_t)(n * CIN1 + c * 32) * cH + (yp - 1)) * cW + (xp - 1);
                #pragma unroll
                for (int i = 0; i < 16; i++) {
                    __half2 h = __floats2half2_rn(src[(size_t)(2 * i) * HW],
                                                  src[(size_t)(2 * i + 1) * HW]);
                    hw[i] = *reinterpret_cast<uint32_t*>(&h);
                }
            } else {
                #pragma unroll
                for (int i = 0; i < 16; i++) hw[i] = 0;
            }
            #pragma unroll
            for (int j = 0; j < 4; j++)
                *reinterpret_cast<uint4*>(dh + c * 32 + j * 8) =
                    *reinterpret_cast<uint4*>(hw + j * 4);
        }
    } else {
        int idx = (blockIdx.x - FEAT_BLOCKS) * 128 + threadIdx.x;
        constexpr int N1 = 9 * COUT1 * CIN1;
        if (idx < N1) {
            int ci = idx % CIN1; int t = idx / CIN1;
            int co = t % COUT1, pos = t / COUT1;
            g_W1[idx] = __float2half(w1[((size_t)co * CIN1 + ci) * 9 + pos]);
        } else if (idx < NW_TOTAL) {
            int k = idx - N1;
            int ci = k % CIN2; int t = k / CIN2;
            int co = t % COUT2, pos = t / COUT2;
            g_W2[k] = __float2half(w2[((size_t)co * CIN2 + ci) * 9 + pos]);
        }
    }
}

// ---------------- HMMA fp16 conv: CTA = 128px x NCO, 8 warps (4M x 2N) -------
// A-chunk-stationary (3 x 130-row halo window staged once per K-chunk).
// ROWSTAGE: W staged per ky-row (3 positions/barrier-interval; best for conv1,
// KR=32). Else W staged per position, KR=64 (best for conv2: A staged only 2x).
// EPI1: smem-bounced coalesced fp16 plane write. Else: fused softmax+upsample.
template<int CIN, int NCO, int KR, bool ROWSTAGE, bool EPI1>
__global__ __launch_bounds__(256, 2) void conv_mma_kernel(
    const __half* __restrict__ Ap, const __half* __restrict__ Wv,
    const float* __restrict__ bias,
    const float* __restrict__ flow, float* __restrict__ out)
{
    constexpr int NKC = CIN / KR;
    constexpr int NKH = KR / 16;
    constexpr int A16 = KR / 8;
    constexpr int P   = KR * 2 + 16;            // 80 / 144: conflict-free pitch
    constexpr int AROWS = 3 * 130;
    constexpr int WN  = NCO / 2;
    constexpr int NT  = NCO / 16;
    constexpr int NPAIR = NT / 2;
    constexpr int ABUF = AROWS * P;
    constexpr int WBUF = (ROWSTAGE ? 3 : 1) * NCO * P;

    extern __shared__ __align__(16) char smem[];
    const uint32_t sA = smem_u32(smem);
    const uint32_t sW = sA + ABUF;

    const int tid = threadIdx.x, lane = tid & 31, wid = tid >> 5;
    const int warpM = wid & 3, warpN = wid >> 2;
    const int gr = lane >> 2;

    const uint32_t aoff = (uint32_t)((lane & 15) * P + (lane >> 4) * 16);
    const uint32_t boff = (uint32_t)((((lane >> 4) << 3) + (lane & 7)) * P + ((lane >> 3) & 1) * 16);
    const uint32_t boff2 = (uint32_t)((lane & 7) * P + ((lane >> 3) & 1) * 16);

    const int x0 = blockIdx.x * 128, y = blockIdx.y, n = blockIdx.z;

    float acc[2][NT][4];
    #pragma unroll
    for (int mi = 0; mi < 2; mi++)
        #pragma unroll
        for (int ni = 0; ni < NT; ni++)
            #pragma unroll
            for (int j = 0; j < 4; j++) acc[mi][ni][j] = 0.0f;

    auto stageA = [&](int kc) {
        const size_t rowb = (size_t)(n * Hp + y) * Wp + x0;
        for (int idx = tid; idx < AROWS * A16; idx += 256) {
            int rr = idx / A16, j = idx % A16;
            int ky = rr / 130, px = rr - ky * 130;
            cpa16(sA + rr * P + j * 16,
                  Ap + (rowb + (size_t)ky * Wp + px) * CIN + kc * KR + j * 8);
        }
    };
    // stage nPos consecutive positions starting at pos0 into buffer buf
    auto stageW = [&](int pos0, int nPos, int kc, int buf) {
        const __half* ws = Wv + (size_t)pos0 * NCO * CIN + kc * KR;
        for (int idx = tid; idx < nPos * NCO * A16; idx += 256) {
            int rr = idx / A16, j = idx % A16;
            cpa16(sW + buf * WBUF + rr * P + j * 16, ws + (size_t)rr * CIN + j * 8);
        }
        asm volatile("cp.async.commit_group;" ::: "memory");
    };

    // compute one (ky,kx) position; W at (sW + buf*WBUF + wslot*NCO*P)
    auto computePos = [&](int ky, int kx, int buf, int wslot) {
        const uint32_t Wb = sW + buf * WBUF + (uint32_t)(wslot * NCO * P);
        const uint32_t arow = (uint32_t)((ky * 130 + kx + warpM * 32) * P);
        #pragma unroll
        for (int kh = 0; kh < NKH; kh++) {
            const uint32_t ko = kh * 32;
            uint32_t a[2][4];
            #pragma unroll
            for (int mi = 0; mi < 2; mi++)
                ldsm_x4(sA + arow + (uint32_t)(mi * 16 * P) + aoff + ko, a[mi]);
            #pragma unroll
            for (int np = 0; np < NPAIR; np++) {
                uint32_t w[4];
                ldsm_x4(Wb + (uint32_t)((warpN * WN + np * 16) * P) + boff + ko, w);
                #pragma unroll
                for (int mi = 0; mi < 2; mi++) {
                    mma_f16(acc[mi][2 * np],     a[mi], w[0], w[1]);
                    mma_f16(acc[mi][2 * np + 1], a[mi], w[2], w[3]);
                }
            }
            if (NT & 1) {
                uint32_t w[2];
                ldsm_x2(Wb + (uint32_t)((warpN * WN + (NT - 1) * 8) * P) + boff2 + ko, w);
                #pragma unroll
                for (int mi = 0; mi < 2; mi++)
                    mma_f16(acc[mi][NT - 1], a[mi], w[0], w[1]);
            }
        }
    };

    for (int kc = 0; kc < NKC; kc++) {
        __syncthreads();
        stageA(kc);
        if (ROWSTAGE) {
            stageW(0, 3, kc, 0);
            asm volatile("cp.async.wait_group 0;" ::: "memory");
            __syncthreads();
            #pragma unroll
            for (int ky = 0; ky < 3; ky++) {
                if (ky < 2) stageW((ky + 1) * 3, 3, kc, (ky + 1) & 1);
                #pragma unroll
                for (int kx = 0; kx < 3; kx++)
                    computePos(ky, kx, ky & 1, kx);
                if (ky < 2)
                    asm volatile("cp.async.wait_group 0;" ::: "memory");
                __syncthreads();
            }
        } else {
            stageW(0, 1, kc, 0);
            asm volatile("cp.async.wait_group 0;" ::: "memory");
            __syncthreads();
            for (int pos = 0; pos < 9; pos++) {
                if (pos < 8) stageW(pos + 1, 1, kc, (pos + 1) & 1);
                computePos(pos / 3, pos % 3, pos & 1, 0);
                if (pos < 8)
                    asm volatile("cp.async.wait_group 0;" ::: "memory");
                __syncthreads();
            }
        }
    }

    const int t2 = (lane & 3) * 2;

    if (EPI1) {
        // ---- smem-bounced coalesced plane write (pitch 136 halves) ----
        __half* sm16 = reinterpret_cast<__half*>(smem);
        __syncthreads();
        #pragma unroll
        for (int mi = 0; mi < 2; mi++)
            #pragma unroll
            for (int rr = 0; rr < 2; rr++) {
                const int pxl = warpM * 32 + mi * 16 + gr + rr * 8;
                #pragma unroll
                for (int ni = 0; ni < NT; ni++) {
                    const int co = warpN * WN + ni * 8 + t2;
                    float v0 = acc[mi][ni][rr * 2 + 0] + __ldg(bias + co);
                    float v1 = acc[mi][ni][rr * 2 + 1] + __ldg(bias + co + 1);
                    v0 = v0 > 0.f ? v0 : 0.1f * v0;
                    v1 = v1 > 0.f ? v1 : 0.1f * v1;
                    __half2 h = __floats2half2_rn(v0, v1);
                    *reinterpret_cast<uint32_t*>(sm16 + pxl * 136 + co) =
                        *reinterpret_cast<uint32_t*>(&h);
                }
            }
        __syncthreads();
        const int px = tid >> 1, hf = tid & 1;
        const size_t flat = ((size_t)(n * Hp) + y + 1) * Wp + (x0 + px) + 1;
        uint4* dst = reinterpret_cast<uint4*>(g_A2 + flat * CIN2 + hf * 64);
        const uint4* srcp = reinterpret_cast<const uint4*>(sm16 + px * 136 + hf * 64);
        #pragma unroll
        for (int j = 0; j < 8; j++) dst[j] = srcp[j];
    } else {
        // ---- fused softmax + convex upsample + pixel shuffle ----
        float* sm = reinterpret_cast<float*>(smem);   // [128 px][145 pitch]
        __syncthreads();
        #pragma unroll
        for (int mi = 0; mi < 2; mi++)
            #pragma unroll
            for (int rr = 0; rr < 2; rr++) {
                const int pxl = warpM * 32 + mi * 16 + gr + rr * 8;
                #pragma unroll
                for (int ni = 0; ni < NT; ni++) {
                    const int co = warpN * WN + ni * 8 + t2;
                    sm[pxl * 145 + co]     = acc[mi][ni][rr * 2 + 0] + __ldg(bias + co);
                    sm[pxl * 145 + co + 1] = acc[mi][ni][rr * 2 + 1] + __ldg(bias + co + 1);
                }
            }
        __syncthreads();

        const int pxl = tid >> 1, bh = tid & 1;
        const int x = x0 + pxl;

        float fpx[9], fpy[9];
        #pragma unroll
        for (int ki = 0; ki < 3; ki++)
            #pragma unroll
            for (int kj = 0; kj < 3; kj++) {
                const int k = ki * 3 + kj;
                const int yy = y + ki - 1, xx = x + kj - 1;
                const bool ok = (unsigned)yy < (unsigned)cH && (unsigned)xx < (unsigned)cW;
                fpx[k] = ok ? 4.0f * __ldg(flow + (size_t)(n * 2 + 0) * HW + yy * cW + xx) : 0.0f;
                fpy[k] = ok ? 4.0f * __ldg(flow + (size_t)(n * 2 + 1) * HW + yy * cW + xx) : 0.0f;
            }

        const int OH = 4 * cH, OW = 4 * cW;
        #pragma unroll
        for (int a = 0; a < 4; a++) {
            #pragma unroll
            for (int b2 = 0; b2 < 2; b2++) {
                const int b = bh * 2 + b2;
                float m[9], mx = -1e30f;
                #pragma unroll
                for (int k = 0; k < 9; k++) {
                    m[k] = 0.25f * sm[pxl * 145 + k * 16 + a * 4 + b];
                    mx = fmaxf(mx, m[k]);
                }
                float s = 0.0f;
                #pragma unroll
                for (int k = 0; k < 9; k++) { m[k] = __expf(m[k] - mx); s += m[k]; }
                const float inv = 1.0f / s;
                float ox = 0.0f, oy = 0.0f;
                #pragma unroll
                for (int k = 0; k < 9; k++) { ox += m[k] * fpx[k]; oy += m[k] * fpy[k]; }
                const int oyi = y * 4 + a, oxi = x * 4 + b;
                out[((size_t)(n * 2 + 0) * OH + oyi) * OW + oxi] = ox * inv;
                out[((size_t)(n * 2 + 1) * OH + oyi) * OW + oxi] = oy * inv;
            }
        }
    }
}

// ---------------------------------------------------------------------------
extern "C" void kernel_launch(void* const* d_in, const int* in_sizes, int n_in,
                              void* d_out, int out_size)
{
    (void)in_sizes; (void)n_in; (void)out_size;
    const float* flow = (const float*)d_in[0];
    const float* feat = (const float*)d_in[1];
    const float* w1   = (const float*)d_in[2];
    const float* b1   = (const float*)d_in[3];
    const float* w2   = (const float*)d_in[4];
    const float* b2   = (const float*)d_in[5];
    float* out = (float*)d_out;

    __half *a1, *a2, *w1s, *w2s;
    cudaGetSymbolAddress((void**)&a1,  g_A1);
    cudaGetSymbolAddress((void**)&a2,  g_A2);
    cudaGetSymbolAddress((void**)&w1s, g_W1);
    cudaGetSymbolAddress((void**)&w2s, g_W2);

    // conv1: KR=32 rowstage: A 390*80 + 2*3*128*80 = 92,640 (>= epi 34,816)
    constexpr int SM1 = 3 * 130 * 80 + 2 * 3 * COUT1 * 80;
    static_assert(SM1 >= 128 * 136 * 2, "epi1 smem");
    // conv2: KR=64 per-pos: A 390*144 + 2*144*144 = 97,632 (>= epi 74,240)
    constexpr int SM2 = 3 * 130 * 144 + 2 * COUT2 * 144;
    static_assert(SM2 >= 128 * 145 * 4, "epilogue smem");

    cudaFuncSetAttribute(conv_mma_kernel<CIN1, COUT1, 32, true, true>,
                         cudaFuncAttributeMaxDynamicSharedMemorySize, SM1);
    cudaFuncSetAttribute(conv_mma_kernel<CIN2, COUT2, 64, false, false>,
                         cudaFuncAttributeMaxDynamicSharedMemorySize, SM2);

    prep_kernel<<<FEAT_BLOCKS + W_BLOCKS, 128>>>(feat, w1, w2);

    conv_mma_kernel<CIN1, COUT1, 32, true, true ><<<dim3(2, cH, cN), 256, SM1>>>(
        a1, w1s, b1, nullptr, nullptr);
    conv_mma_kernel<CIN2, COUT2, 64, false, false><<<dim3(2, cH, cN), 256, SM2>>>(
        a2, w2s, b2, flow, out);
}